// round 10
// baseline (speedup 1.0000x reference)
#include <cuda_runtime.h>
#include <math.h>

#define HH 30
#define WWG 30
#define HW 900
#define DD 256
#define MAXO 16
#define BB 128
#define FPITCH 288   // 261 feature rows padded to 288 (9 K-tiles of 32)
#define PF 16        // pooling prefetch depth

// ---------------- device scratch ----------------
__device__ __align__(16) float g_E[DD * DD];        // W2 @ Wp
__device__ __align__(16) float g_r[DD];             // b2 @ Wp
__device__ __align__(16) float g_W1p[FPITCH * DD];  // W1 padded to 288 rows
__device__ unsigned long long g_bar;                // epoch barrier (monotonic)

// =========================================================================
// Single fused kernel: per-block CCL+features+prep (+E/r/W1pad shards),
// co-resident global barrier, then the proven FFMA mlp body.
// 128 blocks x 256 threads, 1 block/SM (smem-bound) => all co-resident.
// =========================================================================
__global__ __launch_bounds__(256) void fused_kernel(const float* __restrict__ grid_emb,
                                                    const int* __restrict__ grid,
                                                    const float* __restrict__ sr,
                                                    const float* __restrict__ W1,
                                                    const float* __restrict__ W2,
                                                    const float* __restrict__ Wp,
                                                    const float* __restrict__ b2,
                                                    const float* __restrict__ b1,
                                                    const float* __restrict__ gamma,
                                                    const float* __restrict__ beta,
                                                    const float* __restrict__ bp,
                                                    const float* __restrict__ osp,
                                                    float* __restrict__ out) {
    int b = blockIdx.x, tid = threadIdx.x;

    extern __shared__ float sm[];
    float* csT  = sm;               // 288*16 = 4608
    float* wb0  = csT + 4608;       // 8192  (phase A: g/lab/slot/ipool ints)
    float* wb1  = wb0 + 8192;       // 8192  (phase A: fpool 4096)
    float* hsT  = wb1 + 8192;       // 4096  (phase A: w2s for E)
    float* red  = hsT + 4096;       // 32
    float* red2 = red + 32;         // 32
    float* u_s  = red2 + 32;        // 256
    float* q_s  = u_s + 256;        // 256
    float* sn_s = q_s + 256;        // 256
    float* rr_s = sn_s + 256;       // 256
    __shared__ float dots[MAXO], mur[MAXO], rstdr[MAXO];
    __shared__ int vld[MAXO];
    __shared__ unsigned rootbits[32];
    __shared__ int wpre[32];
    __shared__ int s_flag[2];
    __shared__ int nvalid;
    __shared__ int robj[MAXO], rmin[MAXO], rmax[MAXO], cmin[MAXO], cmax[MAXO];
    __shared__ int offs[MAXO + 1];
    __shared__ float s_bdot;

    // ============ PHASE A ============
    // W1 pad slice: 18432 float4 over 128 blocks = 144 each
    {
        int i = b * 144 + tid;
        if (tid < 144) {
            const float4* w14s = (const float4*)W1;   // 16704 real float4s
            float4 v = make_float4(0.f, 0.f, 0.f, 0.f);
            if (i < 16704) v = w14s[i];
            ((float4*)g_W1p)[i] = v;
        }
    }

    // ---- CCL + features for batch b ----
    int* g       = (int*)wb0;       // 900
    int* lab     = g + HW;          // 900
    int* slot_of = lab + HW;        // 900
    int* ipool   = slot_of + HW;    // 1024 (<= 8192 total ints in wb0)
    float* fpool = wb1;             // 16*256

    for (int c = tid; c < HW; c += 256) {
        int v = grid[b * HW + c];
        g[c] = v;
        lab[c] = (v > 0) ? c : HW;
        slot_of[c] = -1;
    }
    if (tid < 32) rootbits[tid] = 0;
    if (tid == 0) { s_flag[0] = 0; s_flag[1] = 0; }
    __syncthreads();

    for (int it = 0; it < 512; it++) {
        int f = it & 1;
        if (tid == 0) s_flag[1 - f] = 0;
        int changed = 0;
        for (int c = tid; c < HW; c += 256) {
            int gc = g[c];
            if (gc > 0) {
                int m = lab[c];
                int col = c % WWG;
                if (c >= WWG && g[c - WWG] == gc) { int t = lab[c - WWG]; if (t < m) m = t; }
                if (c < HW - WWG && g[c + WWG] == gc) { int t = lab[c + WWG]; if (t < m) m = t; }
                if (col > 0 && g[c - 1] == gc) { int t = lab[c - 1]; if (t < m) m = t; }
                if (col < WWG - 1 && g[c + 1] == gc) { int t = lab[c + 1]; if (t < m) m = t; }
#pragma unroll
                for (int hop = 0; hop < 8; hop++) {
                    int p = lab[m];
                    if (p >= m) break;
                    m = p;
                }
                if (m < lab[c]) { lab[c] = m; changed = 1; }
            }
        }
        if (changed) s_flag[f] = 1;
        __syncthreads();
        int chg = s_flag[f];
        __syncthreads();
        if (!chg) break;
    }

    for (int c = tid; c < HW; c += 256)
        if (g[c] > 0 && lab[c] == c) atomicOr(&rootbits[c >> 5], 1u << (c & 31));
    __syncthreads();
    if (tid == 0) {
        int s = 0;
        for (int w = 0; w < 29; w++) { wpre[w] = s; s += __popc(rootbits[w]); }
        nvalid = s < MAXO ? s : MAXO;
    }
    __syncthreads();
    for (int c = tid; c < HW; c += 256) {
        if (g[c] > 0 && lab[c] == c) {
            int w = c >> 5;
            int rank = wpre[w] + __popc(rootbits[w] & ((1u << (c & 31)) - 1u));
            if (rank < MAXO) { robj[rank] = c; slot_of[c] = rank; }
        }
    }
    if (tid < MAXO) { rmin[tid] = HH; rmax[tid] = -1; cmin[tid] = WWG; cmax[tid] = -1; }
    __syncthreads();
    for (int c = tid; c < HW; c += 256) {
        if (g[c] > 0) {
            int s = slot_of[lab[c]];
            if (s >= 0) {
                int r = c / WWG, col = c % WWG;
                atomicMin(&rmin[s], r); atomicMax(&rmax[s], r);
                atomicMin(&cmin[s], col); atomicMax(&cmax[s], col);
            }
        }
    }
    __syncthreads();

    int nv = nvalid;
    if (tid == 0) {
        int off = 0;
        for (int k = 0; k < nv; k++) {
            offs[k] = off;
            off += (rmax[k] + 1 - rmin[k]) * (cmax[k] + 1 - cmin[k]);
        }
        offs[nv] = off;
    }
    for (int i = tid; i < MAXO * DD; i += 256) fpool[i] = 0.f;
    for (int i = tid; i < FPITCH * MAXO; i += 256) csT[i] = 0.f;
    if (tid < MAXO) vld[tid] = (tid < nv) ? 1 : 0;
    __syncthreads();

    {
        int total = offs[nv];
        float run = 0.f;
        int prev = -1;
        const float* gbase = grid_emb + (size_t)b * HW * DD + tid;
        for (int base = 0; base < total; base += 1024) {
            int n = min(1024, total - base);
            for (int e = tid; e < n; e += 256) {
                int ge = base + e;
                int k = 0;
                while (k + 1 < nv && ge >= offs[k + 1]) k++;
                int local = ge - offs[k];
                int bw = cmax[k] + 1 - cmin[k];
                int li = local / bw, lj = local - li * bw;
                int cell = (rmin[k] + li) * WWG + cmin[k] + lj;
                ipool[e] = (k << 16) | cell;
            }
            __syncthreads();
            for (int e0b = 0; e0b < n; e0b += PF) {
                int m = n - e0b; if (m > PF) m = PF;
                float v[PF]; int kk[PF];
#pragma unroll
                for (int j = 0; j < PF; j++) {
                    if (j < m) {
                        int ent = ipool[e0b + j];
                        kk[j] = ent >> 16;
                        v[j] = gbase[(size_t)(ent & 0xffff) * DD];
                    }
                }
#pragma unroll
                for (int j = 0; j < PF; j++) {
                    if (j < m) {
                        if (kk[j] != prev) {
                            if (prev >= 0) fpool[prev * DD + tid] += run;
                            run = 0.f;
                            prev = kk[j];
                        }
                        run += v[j];
                    }
                }
            }
            __syncthreads();
        }
        if (prev >= 0) fpool[prev * DD + tid] += run;
    }
    __syncthreads();

    // features -> csT ([feat][obj] layout, as proven mlp expects)
    for (int k = 0; k < nv; k++) {
        int y = rmin[k], x = cmin[k];
        int h = rmax[k] + 1 - y, w = cmax[k] + 1 - x;
        csT[tid * MAXO + k] = fpool[k * DD + tid] / (float)(h * w);
        if (tid < 5) {
            float v;
            int color = g[robj[k]];
            if (tid == 0)      v = (float)color * (1.0f / 9.0f);
            else if (tid == 1) v = (float)x * (1.0f / WWG);
            else if (tid == 2) v = (float)y * (1.0f / HH);
            else if (tid == 3) v = (float)w * (1.0f / WWG);
            else               v = (float)h * (1.0f / HH);
            csT[(DD + tid) * MAXO + k] = v;
        }
    }
    __syncthreads();

    // ---- prep: sn, bdot, q, u (all into smem) ----
    {
        float s = 0.f;
        const float* base = sr + (size_t)b * 8 * DD + tid;
#pragma unroll
        for (int j = 0; j < 8; j++) s += base[j * DD];
        s *= 0.125f;
        rr_s[tid] = s * s; __syncthreads();
        for (int off = 128; off; off >>= 1) { if (tid < off) rr_s[tid] += rr_s[tid + off]; __syncthreads(); }
        float nrm = sqrtf(rr_s[0]);
        __syncthreads();
        float snv = s / fmaxf(nrm, 1e-8f);
        sn_s[tid] = snv;
        rr_s[tid] = snv * b2[tid]; __syncthreads();
        for (int off = 128; off; off >>= 1) { if (tid < off) rr_s[tid] += rr_s[tid + off]; __syncthreads(); }
        if (tid == 0) s_bdot = rr_s[0];

        float acc = 0.f;
#pragma unroll 8
        for (int d = 0; d < DD; d++) acc += sn_s[d] * Wp[d * DD + tid];
        q_s[tid] = acc;

        int wid = tid >> 5, lane = tid & 31;
        for (int d = wid; d < DD; d += 8) {
            float a = 0.f;
            const float* wr = W2 + d * DD;
#pragma unroll 4
            for (int e2 = lane; e2 < DD; e2 += 32) a += wr[e2] * sn_s[e2];
#pragma unroll
            for (int off = 16; off; off >>= 1) a += __shfl_down_sync(0xffffffffu, a, off);
            if (lane == 0) u_s[d] = a;
        }
    }
    __syncthreads();

    // ---- E shard: blocks [0,64) compute rows 4b..4b+4 of E = W2@Wp ----
    if (b < 64) {
        float* w2s = hsT;   // 4*256 floats
        int d0 = b * 4, e = tid;
        for (int i = tid; i < 4 * DD; i += 256) w2s[i] = W2[d0 * DD + i];
        __syncthreads();
        float a0 = 0.f, a1 = 0.f, a2 = 0.f, a3 = 0.f;
#pragma unroll 4
        for (int k = 0; k < DD; k++) {
            float wp = Wp[k * DD + e];
            a0 += w2s[0 * DD + k] * wp;
            a1 += w2s[1 * DD + k] * wp;
            a2 += w2s[2 * DD + k] * wp;
            a3 += w2s[3 * DD + k] * wp;
        }
        g_E[(d0 + 0) * DD + e] = a0;
        g_E[(d0 + 1) * DD + e] = a1;
        g_E[(d0 + 2) * DD + e] = a2;
        g_E[(d0 + 3) * DD + e] = a3;
    } else if (b == 64) {
        float a = 0.f;
#pragma unroll 8
        for (int k = 0; k < DD; k++) a += b2[k] * Wp[k * DD + tid];
        g_r[tid] = a;
    }
    __syncthreads();

    // ============ GLOBAL EPOCH BARRIER (all 128 blocks co-resident) ============
    if (tid == 0) {
        __threadfence();   // release g_E / g_r / g_W1p
        unsigned long long t = atomicAdd(&g_bar, 1ULL);
        unsigned long long target = (t / 128ULL + 1ULL) * 128ULL;
        while (*((volatile unsigned long long*)&g_bar) < target) {
            __nanosleep(64);
        }
        __threadfence();   // acquire
    }
    __syncthreads();

    // ============ PHASE B: proven mlp body ============
    int rg = tid >> 6, cg = tid & 63;
    int r0 = rg * 4, e0 = cg * 4;
    int wid = tid >> 5, lane = tid & 31;

    const float4* w14 = (const float4*)g_W1p;  // 9 tiles of 2048 float4
    const float4* e4  = (const float4*)g_E;    // 8 tiles of 2048 float4

    {
        float4 pf[8];
#pragma unroll
        for (int j = 0; j < 8; j++) pf[j] = w14[tid + j * 256];
#pragma unroll
        for (int j = 0; j < 8; j++) ((float4*)wb0)[tid + j * 256] = pf[j];
    }
    __syncthreads();

    float bdot = s_bdot;
    float os = osp[0];

    float acc[4][4];
#pragma unroll
    for (int i = 0; i < 4; i++)
#pragma unroll
        for (int j = 0; j < 4; j++) acc[i][j] = 0.f;

    for (int t = 0; t < 9; t++) {
        float4 pf[8];
        if (t < 8) {
            int base = (t + 1) * 2048;
#pragma unroll
            for (int j = 0; j < 8; j++) pf[j] = w14[base + tid + j * 256];
        }
        const float* wcur = (t & 1) ? wb1 : wb0;
#pragma unroll
        for (int kk = 0; kk < 32; kk++) {
            float4 c4 = *(const float4*)&csT[(t * 32 + kk) * MAXO + r0];
            float4 w4 = *(const float4*)&wcur[kk * 256 + e0];
            float ca[4] = {c4.x, c4.y, c4.z, c4.w};
            float wa[4] = {w4.x, w4.y, w4.z, w4.w};
#pragma unroll
            for (int i = 0; i < 4; i++)
#pragma unroll
                for (int j = 0; j < 4; j++) acc[i][j] += ca[i] * wa[j];
        }
        __syncthreads();
        if (t < 8) {
            float* wn = (t & 1) ? wb0 : wb1;
#pragma unroll
            for (int j = 0; j < 8; j++) ((float4*)wn)[tid + j * 256] = pf[j];
            __syncthreads();
        }
    }

    float4 b14 = *(const float4*)&b1[e0];
    float bb[4] = {b14.x, b14.y, b14.z, b14.w};
    float h[4][4];
#pragma unroll
    for (int i = 0; i < 4; i++)
#pragma unroll
        for (int j = 0; j < 4; j++) {
            float xx = acc[i][j] + bb[j];
            h[i][j] = 0.5f * xx * (1.0f + erff(xx * 0.70710678118654752f));
        }
#pragma unroll
    for (int j = 0; j < 4; j++) {
        float4 v = make_float4(h[0][j], h[1][j], h[2][j], h[3][j]);
        *(float4*)&hsT[(e0 + j) * MAXO + r0] = v;
    }

    float uu[4] = {u_s[e0], u_s[e0 + 1], u_s[e0 + 2], u_s[e0 + 3]};
    float p[4];
#pragma unroll
    for (int i = 0; i < 4; i++)
        p[i] = h[i][0] * uu[0] + h[i][1] * uu[1] + h[i][2] * uu[2] + h[i][3] * uu[3];
#pragma unroll
    for (int off = 16; off; off >>= 1)
#pragma unroll
        for (int i = 0; i < 4; i++) p[i] += __shfl_down_sync(0xffffffffu, p[i], off);
    if (lane == 0) {
#pragma unroll
        for (int i = 0; i < 4; i++) red[(r0 + i) * 2 + (wid & 1)] = p[i];
    }
    __syncthreads();
    if (tid < MAXO) dots[tid] = red[tid * 2] + red[tid * 2 + 1] + bdot;

    {
        float4 pf[8];
#pragma unroll
        for (int j = 0; j < 8; j++) pf[j] = e4[tid + j * 256];
#pragma unroll
        for (int j = 0; j < 8; j++) ((float4*)wb0)[tid + j * 256] = pf[j];
    }
    __syncthreads();

    float a2[4][4];
#pragma unroll
    for (int i = 0; i < 4; i++)
#pragma unroll
        for (int j = 0; j < 4; j++) a2[i][j] = 0.f;

    for (int t = 0; t < 8; t++) {
        float4 pf[8];
        if (t < 7) {
            int base = (t + 1) * 2048;
#pragma unroll
            for (int j = 0; j < 8; j++) pf[j] = e4[base + tid + j * 256];
        }
        const float* wcur = (t & 1) ? wb1 : wb0;
#pragma unroll
        for (int kk = 0; kk < 32; kk++) {
            float4 h4 = *(const float4*)&hsT[(t * 32 + kk) * MAXO + r0];
            float4 w4 = *(const float4*)&wcur[kk * 256 + e0];
            float ha[4] = {h4.x, h4.y, h4.z, h4.w};
            float wa[4] = {w4.x, w4.y, w4.z, w4.w};
#pragma unroll
            for (int i = 0; i < 4; i++)
#pragma unroll
                for (int j = 0; j < 4; j++) a2[i][j] += ha[i] * wa[j];
        }
        __syncthreads();
        if (t < 7) {
            float* wn = (t & 1) ? wb0 : wb1;
#pragma unroll
            for (int j = 0; j < 8; j++) ((float4*)wn)[tid + j * 256] = pf[j];
            __syncthreads();
        }
    }

    float4 bp4 = *(const float4*)&bp[e0];
    float4 rv4 = *(const float4*)&g_r[e0];
    float bpp[4] = {bp4.x, bp4.y, bp4.z, bp4.w};
    float rrv[4] = {rv4.x, rv4.y, rv4.z, rv4.w};
    float qq[4] = {q_s[e0], q_s[e0 + 1], q_s[e0 + 2], q_s[e0 + 3]};
    float pre[4][4];
#pragma unroll
    for (int i = 0; i < 4; i++) {
        float dt = dots[r0 + i];
        int v = vld[r0 + i];
#pragma unroll
        for (int j = 0; j < 4; j++) {
            float pv = os * (a2[i][j] + rrv[j] - dt * qq[j]) + bpp[j];
            pre[i][j] = v ? pv : bpp[j];
        }
    }

    float ps[4], pq[4];
#pragma unroll
    for (int i = 0; i < 4; i++) {
        ps[i] = pre[i][0] + pre[i][1] + pre[i][2] + pre[i][3];
        pq[i] = pre[i][0] * pre[i][0] + pre[i][1] * pre[i][1] +
                pre[i][2] * pre[i][2] + pre[i][3] * pre[i][3];
    }
#pragma unroll
    for (int off = 16; off; off >>= 1)
#pragma unroll
        for (int i = 0; i < 4; i++) {
            ps[i] += __shfl_down_sync(0xffffffffu, ps[i], off);
            pq[i] += __shfl_down_sync(0xffffffffu, pq[i], off);
        }
    if (lane == 0) {
#pragma unroll
        for (int i = 0; i < 4; i++) {
            red[(r0 + i) * 2 + (wid & 1)] = ps[i];
            red2[(r0 + i) * 2 + (wid & 1)] = pq[i];
        }
    }
    __syncthreads();
    if (tid < MAXO) {
        float m = (red[tid * 2] + red[tid * 2 + 1]) * (1.0f / DD);
        mur[tid] = m;
        float va = (red2[tid * 2] + red2[tid * 2 + 1]) * (1.0f / DD) - m * m;
        rstdr[tid] = rsqrtf(va + 1e-5f);
    }
    __syncthreads();

    float4 g4 = *(const float4*)&gamma[e0];
    float4 be4 = *(const float4*)&beta[e0];
    float gg[4] = {g4.x, g4.y, g4.z, g4.w};
    float bee[4] = {be4.x, be4.y, be4.z, be4.w};
#pragma unroll
    for (int i = 0; i < 4; i++) {
        float m = mur[r0 + i], rs = rstdr[r0 + i];
        float4 o;
        o.x = (pre[i][0] - m) * rs * gg[0] + bee[0];
        o.y = (pre[i][1] - m) * rs * gg[1] + bee[1];
        o.z = (pre[i][2] - m) * rs * gg[2] + bee[2];
        o.w = (pre[i][3] - m) * rs * gg[3] + bee[3];
        *(float4*)&out[((size_t)(b * MAXO + r0 + i)) * DD + e0] = o;
    }
}

#define FUSED_SMEM ((4608 + 8192 + 8192 + 4096 + 32 + 32 + 256 + 256 + 256 + 256) * 4)

// =========================================================================
extern "C" void kernel_launch(void* const* d_in, const int* in_sizes, int n_in,
                              void* d_out, int out_size) {
    const float* grid_emb = (const float*)d_in[0];
    const int*   grid     = (const int*)d_in[1];
    const float* sr       = (const float*)d_in[2];
    const float* W1       = (const float*)d_in[3];
    const float* b1       = (const float*)d_in[4];
    const float* W2       = (const float*)d_in[5];
    const float* b2       = (const float*)d_in[6];
    const float* Wp       = (const float*)d_in[7];
    const float* bp       = (const float*)d_in[8];
    const float* gamma    = (const float*)d_in[9];
    const float* beta     = (const float*)d_in[10];
    const float* os       = (const float*)d_in[11];

    cudaFuncSetAttribute(fused_kernel, cudaFuncAttributeMaxDynamicSharedMemorySize, FUSED_SMEM);

    fused_kernel<<<BB, 256, FUSED_SMEM>>>(grid_emb, grid, sr, W1, W2, Wp, b2,
                                          b1, gamma, beta, bp, os, (float*)d_out);
}

// round 11
// speedup vs baseline: 1.0180x; 1.0180x over previous
#include <cuda_runtime.h>
#include <cuda_bf16.h>
#include <math.h>

#define HH 30
#define WWG 30
#define HW 900
#define DD 256
#define MAXO 16
#define BB 128
#define FPITCH 288   // 261 feature rows padded to 288 (18 K-tiles of 16)
#define CHUNK 1024
#define PF 8

// ---------------- device scratch ----------------
__device__ __align__(16) float g_comb[BB * FPITCH * MAXO];  // [b][feat][k]
__device__ __align__(16) float g_u[BB * DD];
__device__ __align__(16) float g_q[BB * DD];
__device__ float g_bdot[BB];
__device__ __align__(16) float g_r[DD];                     // b2 @ Wp
__device__ int   g_valid[BB * MAXO];
// transposed bf16 hi/lo weights: [n][k]
__device__ __align__(16) __nv_bfloat16 g_W1th[DD * FPITCH];
__device__ __align__(16) __nv_bfloat16 g_W1tl[DD * FPITCH];
__device__ __align__(16) __nv_bfloat16 g_Eth[DD * DD];
__device__ __align__(16) __nv_bfloat16 g_Etl[DD * DD];

__device__ __forceinline__ void bsplit(float x, __nv_bfloat16& h, __nv_bfloat16& l) {
    h = __float2bfloat16(x);
    l = __float2bfloat16(x - __bfloat162float(h));
}
__device__ __forceinline__ unsigned bpack(float a, float b) {
    unsigned lo = __bfloat16_as_ushort(__float2bfloat16(a));
    unsigned hi = __bfloat16_as_ushort(__float2bfloat16(b));
    return (hi << 16) | lo;
}
__device__ __forceinline__ unsigned bpack2(__nv_bfloat16 a, __nv_bfloat16 b) {
    return ((unsigned)__bfloat16_as_ushort(b) << 16) | __bfloat16_as_ushort(a);
}
__device__ __forceinline__ void mma16816(float c[4], const unsigned a[4],
                                         unsigned b0, unsigned b1) {
    asm volatile(
        "mma.sync.aligned.m16n8k16.row.col.f32.bf16.bf16.f32 "
        "{%0,%1,%2,%3},{%4,%5,%6,%7},{%8,%9},{%0,%1,%2,%3};"
        : "+f"(c[0]), "+f"(c[1]), "+f"(c[2]), "+f"(c[3])
        : "r"(a[0]), "r"(a[1]), "r"(a[2]), "r"(a[3]), "r"(b0), "r"(b1));
}
__device__ __forceinline__ float gelu(float x) {
    return 0.5f * x * (1.0f + erff(x * 0.70710678118654752f));
}

// =========================================================================
// Fused pre-kernel, 1024 threads/block (R9-proven; E/W1 branches now emit
// transposed bf16 hi/lo).
// blockIdx: [0,128) ccl, [128,256) prep, [256,288) E, 288 r, [289,307) W1.
// =========================================================================
__global__ __launch_bounds__(1024) void pre_kernel(const float* __restrict__ grid_emb,
                                                   const int* __restrict__ grid,
                                                   const float* __restrict__ sr,
                                                   const float* __restrict__ W1,
                                                   const float* __restrict__ W2,
                                                   const float* __restrict__ Wp,
                                                   const float* __restrict__ b2) {
    int br = blockIdx.x, tid = threadIdx.x;

    __shared__ __align__(16) char spool[46080];
    __shared__ unsigned rootbits[32];
    __shared__ int wpre[32];
    __shared__ int s_flag[2];
    __shared__ int nvalid;
    __shared__ int robj[MAXO], rmin[MAXO], rmax[MAXO], cmin[MAXO], cmax[MAXO];
    __shared__ int offs[MAXO + 1];

    if (br < BB) {
        int* g       = (int*)spool;
        int* lab     = g + HW;
        int* slot_of = lab + HW;
        float* fpool = (float*)(spool + 10816);
        int* ipool   = (int*)(spool + 27200);

        int b = br;
        for (int c = tid; c < HW; c += 1024) {
            int v = grid[b * HW + c];
            g[c] = v;
            lab[c] = (v > 0) ? c : HW;
            slot_of[c] = -1;
        }
        if (tid < 32) rootbits[tid] = 0;
        if (tid == 0) { s_flag[0] = 0; s_flag[1] = 0; }
        __syncthreads();

        for (int it = 0; it < 512; it++) {
            int f = it & 1;
            if (tid == 0) s_flag[1 - f] = 0;
            int changed = 0;
            for (int c = tid; c < HW; c += 1024) {
                int gc = g[c];
                if (gc > 0) {
                    int m = lab[c];
                    int col = c % WWG;
                    if (c >= WWG && g[c - WWG] == gc) { int t = lab[c - WWG]; if (t < m) m = t; }
                    if (c < HW - WWG && g[c + WWG] == gc) { int t = lab[c + WWG]; if (t < m) m = t; }
                    if (col > 0 && g[c - 1] == gc) { int t = lab[c - 1]; if (t < m) m = t; }
                    if (col < WWG - 1 && g[c + 1] == gc) { int t = lab[c + 1]; if (t < m) m = t; }
#pragma unroll
                    for (int hop = 0; hop < 8; hop++) {
                        int p = lab[m];
                        if (p >= m) break;
                        m = p;
                    }
                    if (m < lab[c]) { lab[c] = m; changed = 1; }
                }
            }
            if (changed) s_flag[f] = 1;
            __syncthreads();
            int chg = s_flag[f];
            __syncthreads();
            if (!chg) break;
        }

        for (int c = tid; c < HW; c += 1024)
            if (g[c] > 0 && lab[c] == c) atomicOr(&rootbits[c >> 5], 1u << (c & 31));
        __syncthreads();
        if (tid == 0) {
            int s = 0;
            for (int w = 0; w < 29; w++) { wpre[w] = s; s += __popc(rootbits[w]); }
            nvalid = s < MAXO ? s : MAXO;
        }
        __syncthreads();
        for (int c = tid; c < HW; c += 1024) {
            if (g[c] > 0 && lab[c] == c) {
                int w = c >> 5;
                int rank = wpre[w] + __popc(rootbits[w] & ((1u << (c & 31)) - 1u));
                if (rank < MAXO) { robj[rank] = c; slot_of[c] = rank; }
            }
        }
        if (tid < MAXO) { rmin[tid] = HH; rmax[tid] = -1; cmin[tid] = WWG; cmax[tid] = -1; }
        __syncthreads();
        for (int c = tid; c < HW; c += 1024) {
            if (g[c] > 0) {
                int s = slot_of[lab[c]];
                if (s >= 0) {
                    int r = c / WWG, col = c % WWG;
                    atomicMin(&rmin[s], r); atomicMax(&rmax[s], r);
                    atomicMin(&cmin[s], col); atomicMax(&cmax[s], col);
                }
            }
        }
        __syncthreads();

        int nv = nvalid;
        if (tid == 0) {
            int off = 0;
            for (int k = 0; k < nv; k++) {
                offs[k] = off;
                off += (rmax[k] + 1 - rmin[k]) * (cmax[k] + 1 - cmin[k]);
            }
            offs[nv] = off;
        }
        for (int i = tid; i < MAXO * DD; i += 1024) fpool[i] = 0.f;
        __syncthreads();

        int total = offs[nv];
        int ch = tid & 255, grp = tid >> 8;
        const float* gbase = grid_emb + (size_t)b * HW * DD + ch;
        for (int base = 0; base < total; base += CHUNK) {
            int n = min(CHUNK, total - base);
            for (int e = tid; e < n; e += 1024) {
                int ge = base + e;
                int k = 0;
                while (k + 1 < nv && ge >= offs[k + 1]) k++;
                int local = ge - offs[k];
                int bw = cmax[k] + 1 - cmin[k];
                int li = local / bw, lj = local - li * bw;
                int cell = (rmin[k] + li) * WWG + cmin[k] + lj;
                ipool[e] = (k << 16) | cell;
            }
            __syncthreads();
            int n4 = (n + 3) >> 2;
            int s0 = grp * n4, s1 = min(n, s0 + n4);
            float run = 0.f;
            int prev = -1;
            for (int e0b = s0; e0b < s1; e0b += PF) {
                int m = s1 - e0b; if (m > PF) m = PF;
                float v[PF]; int kk[PF];
#pragma unroll
                for (int j = 0; j < PF; j++) {
                    if (j < m) {
                        int ent = ipool[e0b + j];
                        kk[j] = ent >> 16;
                        v[j] = gbase[(size_t)(ent & 0xffff) * DD];
                    }
                }
#pragma unroll
                for (int j = 0; j < PF; j++) {
                    if (j < m) {
                        if (kk[j] != prev) {
                            if (prev >= 0) atomicAdd(&fpool[prev * DD + ch], run);
                            run = 0.f;
                            prev = kk[j];
                        }
                        run += v[j];
                    }
                }
            }
            if (prev >= 0) atomicAdd(&fpool[prev * DD + ch], run);
            __syncthreads();
        }

        float* cb = g_comb + (size_t)b * FPITCH * MAXO;
        for (int i = tid; i < FPITCH * MAXO; i += 1024) cb[i] = 0.f;
        if (tid < MAXO) g_valid[b * MAXO + tid] = (tid < nv) ? 1 : 0;
        __syncthreads();
        if (tid < DD) {
            for (int k = 0; k < nv; k++) {
                int y = rmin[k], x = cmin[k];
                int h = rmax[k] + 1 - y, w = cmax[k] + 1 - x;
                cb[tid * MAXO + k] = fpool[k * DD + tid] / (float)(h * w);
                if (tid < 5) {
                    float v;
                    int color = g[robj[k]];
                    if (tid == 0)      v = (float)color * (1.0f / 9.0f);
                    else if (tid == 1) v = (float)x * (1.0f / WWG);
                    else if (tid == 2) v = (float)y * (1.0f / HH);
                    else if (tid == 3) v = (float)w * (1.0f / WWG);
                    else               v = (float)h * (1.0f / HH);
                    cb[(DD + tid) * MAXO + k] = v;
                }
            }
        }
    } else if (br < 2 * BB) {
        // ---------------- prep: sn, u, q, bdot ----------------
        int b = br - BB;
        float* sn   = (float*)spool;
        float* sred = sn + DD;
        float s = 0.f;
        if (tid < DD) {
            const float* base = sr + (size_t)b * 8 * DD + tid;
#pragma unroll
            for (int j = 0; j < 8; j++) s += base[j * DD];
            s *= 0.125f;
            sred[tid] = s * s;
        }
        __syncthreads();
        for (int off = 128; off; off >>= 1) {
            if (tid < off) sred[tid] += sred[tid + off];
            __syncthreads();
        }
        float nrm = sqrtf(sred[0]);
        __syncthreads();
        float snv = s / fmaxf(nrm, 1e-8f);
        if (tid < DD) { sn[tid] = snv; sred[tid] = snv * b2[tid]; }
        __syncthreads();
        for (int off = 128; off; off >>= 1) {
            if (tid < off) sred[tid] += sred[tid + off];
            __syncthreads();
        }
        if (tid == 0) g_bdot[b] = sred[0];

        if (tid < DD) {
            float acc = 0.f;
#pragma unroll 8
            for (int d = 0; d < DD; d++) acc += sn[d] * Wp[d * DD + tid];
            g_q[b * DD + tid] = acc;
        }

        int wid = tid >> 5, lane = tid & 31;
        for (int d = wid; d < DD; d += 32) {
            float a = 0.f;
            const float* wr = W2 + d * DD;
#pragma unroll 4
            for (int e2 = lane; e2 < DD; e2 += 32) a += wr[e2] * sn[e2];
#pragma unroll
            for (int off = 16; off; off >>= 1) a += __shfl_down_sync(0xffffffffu, a, off);
            if (lane == 0) g_u[b * DD + d] = a;
        }
    } else if (br < 2 * BB + 32) {
        // ------- E rows -> transposed bf16 hi/lo: Et[n][k] = (W2@Wp)[k][n] -------
        int d0 = (br - 2 * BB) * 8;
        int e = tid & 255, sub = tid >> 8;
        int r0 = sub * 2;
        float* wpt = (float*)spool;
        float* w2s = (float*)(spool + 32768);
        for (int i = tid; i < 8 * DD; i += 1024) w2s[i] = W2[d0 * DD + i];
        const float4* wp4 = (const float4*)Wp;
        float4 pf0 = wp4[tid], pf1 = wp4[tid + 1024];
        __syncthreads();
        float a0 = 0.f, a1 = 0.f;
        for (int t = 0; t < 8; t++) {
            ((float4*)wpt)[tid] = pf0;
            ((float4*)wpt)[tid + 1024] = pf1;
            __syncthreads();
            if (t < 7) {
                pf0 = wp4[(t + 1) * 2048 + tid];
                pf1 = wp4[(t + 1) * 2048 + tid + 1024];
            }
#pragma unroll 8
            for (int k = 0; k < 32; k++) {
                float wp = wpt[k * 256 + e];
                a0 += w2s[r0 * DD + t * 32 + k] * wp;
                a1 += w2s[(r0 + 1) * DD + t * 32 + k] * wp;
            }
            __syncthreads();
        }
        __nv_bfloat16 h, l;
        bsplit(a0, h, l);
        g_Eth[e * DD + d0 + r0] = h; g_Etl[e * DD + d0 + r0] = l;
        bsplit(a1, h, l);
        g_Eth[e * DD + d0 + r0 + 1] = h; g_Etl[e * DD + d0 + r0 + 1] = l;
    } else if (br == 2 * BB + 32) {
        if (tid < DD) {
            float a = 0.f;
#pragma unroll 8
            for (int k = 0; k < DD; k++) a += b2[k] * Wp[k * DD + tid];
            g_r[tid] = a;
        }
    } else {
        // ---- W1 (261x256) -> transposed bf16 hi/lo [n][288], zero-padded ----
        int i = (br - (2 * BB + 33)) * 1024 + tid;   // float4 idx 0..18431
        if (i < (FPITCH * DD) / 4) {
            const float4* w14 = (const float4*)W1;   // 16704 real float4s
            float4 v = make_float4(0.f, 0.f, 0.f, 0.f);
            if (i < 16704) v = w14[i];
            int k = i >> 6;            // k row of W1
            int n0 = (i & 63) * 4;     // starting n col
            float vals[4] = {v.x, v.y, v.z, v.w};
#pragma unroll
            for (int c = 0; c < 4; c++) {
                __nv_bfloat16 h, l;
                bsplit(vals[c], h, l);
                g_W1th[(n0 + c) * FPITCH + k] = h;
                g_W1tl[(n0 + c) * FPITCH + k] = l;
            }
        }
    }
}
#define PRE_GRID (2 * BB + 33 + 18)   // 307

// =========================================================================
// Tensor-core MLP: mma.sync m16n8k16 bf16, 3-pass hi/lo split.
// One block = one batch (M=16), 8 warps x 4 n-tiles = 256 cols.
// =========================================================================
__global__ __launch_bounds__(256) void mlp_kernel(const float* __restrict__ b1v,
                                                  const float* __restrict__ gv,
                                                  const float* __restrict__ btv,
                                                  const float* __restrict__ bpv,
                                                  const float* __restrict__ osp,
                                                  float* __restrict__ out) {
    int b = blockIdx.x, tid = threadIdx.x;
    int warp = tid >> 5, lane = tid & 31;
    int g = lane >> 2, tl = lane & 3;

    extern __shared__ char smraw[];
    __nv_bfloat16* A1h = (__nv_bfloat16*)(smraw);            // 16 x 296
    __nv_bfloat16* A1l = (__nv_bfloat16*)(smraw + 9472);
    __nv_bfloat16* A2h = (__nv_bfloat16*)(smraw + 18944);    // 16 x 264
    __nv_bfloat16* A2l = (__nv_bfloat16*)(smraw + 27392);
    __nv_bfloat16* Bh  = (__nv_bfloat16*)(smraw + 35840);    // 256 x 24 (16 used + pad)
    __nv_bfloat16* Bl  = (__nv_bfloat16*)(smraw + 48128);
    float* u_s  = (float*)(smraw + 60416);
    float* q_s  = (float*)(smraw + 61440);
    float* r_s  = (float*)(smraw + 62464);
    float* bp_s = (float*)(smraw + 63488);
    float* gm_s = (float*)(smraw + 64512);
    float* bt_s = (float*)(smraw + 65536);
    float* b1_s = (float*)(smraw + 66560);
    float* redA = (float*)(smraw + 67584);   // [16][8]
    float* redB = (float*)(smraw + 68096);   // [16][8]
    __shared__ float dots[MAXO], mur[MAXO], rstd[MAXO], s_bd[2];
    __shared__ int vld[MAXO];

    // ---- stage A1 (combined -> bf16 hi/lo [m][k]) + constants ----
    const float* cbase = g_comb + (size_t)b * FPITCH * MAXO;
    for (int i = tid; i < FPITCH * MAXO; i += 256) {
        float x = cbase[i];
        int feat = i >> 4, obj = i & 15;
        __nv_bfloat16 h, l;
        bsplit(x, h, l);
        A1h[obj * 296 + feat] = h;
        A1l[obj * 296 + feat] = l;
    }
    u_s[tid] = g_u[b * DD + tid];
    q_s[tid] = g_q[b * DD + tid];
    r_s[tid] = g_r[tid];
    bp_s[tid] = bpv[tid];
    gm_s[tid] = gv[tid];
    bt_s[tid] = btv[tid];
    b1_s[tid] = b1v[tid];
    if (tid < MAXO) vld[tid] = g_valid[b * MAXO + tid];
    if (tid == 0) { s_bd[0] = g_bdot[b]; s_bd[1] = osp[0]; }

    // ============ GEMM1: hidden = gelu(A1 @ W1 + b1), K=288 (18 tiles) ============
    float c1[4][4];
#pragma unroll
    for (int nt = 0; nt < 4; nt++)
#pragma unroll
        for (int j = 0; j < 4; j++) c1[nt][j] = 0.f;

    uint4 ph0 = *(const uint4*)(g_W1th + tid * FPITCH);
    uint4 ph1 = *(const uint4*)(g_W1th + tid * FPITCH + 8);
    uint4 pl0 = *(const uint4*)(g_W1tl + tid * FPITCH);
    uint4 pl1 = *(const uint4*)(g_W1tl + tid * FPITCH + 8);

    for (int t = 0; t < 18; t++) {
        *(uint4*)(Bh + tid * 24) = ph0;
        *(uint4*)(Bh + tid * 24 + 8) = ph1;
        *(uint4*)(Bl + tid * 24) = pl0;
        *(uint4*)(Bl + tid * 24 + 8) = pl1;
        __syncthreads();
        if (t < 17) {
            int o = tid * FPITCH + 16 * (t + 1);
            ph0 = *(const uint4*)(g_W1th + o);
            ph1 = *(const uint4*)(g_W1th + o + 8);
            pl0 = *(const uint4*)(g_W1tl + o);
            pl1 = *(const uint4*)(g_W1tl + o + 8);
        }
        unsigned ah[4], al[4];
        {
            int k0 = 16 * t + 2 * tl;
            ah[0] = *(const unsigned*)(A1h + g * 296 + k0);
            ah[1] = *(const unsigned*)(A1h + (g + 8) * 296 + k0);
            ah[2] = *(const unsigned*)(A1h + g * 296 + k0 + 8);
            ah[3] = *(const unsigned*)(A1h + (g + 8) * 296 + k0 + 8);
            al[0] = *(const unsigned*)(A1l + g * 296 + k0);
            al[1] = *(const unsigned*)(A1l + (g + 8) * 296 + k0);
            al[2] = *(const unsigned*)(A1l + g * 296 + k0 + 8);
            al[3] = *(const unsigned*)(A1l + (g + 8) * 296 + k0 + 8);
        }
#pragma unroll
        for (int nt = 0; nt < 4; nt++) {
            int n = (warp * 4 + nt) * 8 + g;
            unsigned bh0 = *(const unsigned*)(Bh + n * 24 + 2 * tl);
            unsigned bh1 = *(const unsigned*)(Bh + n * 24 + 8 + 2 * tl);
            unsigned bl0 = *(const unsigned*)(Bl + n * 24 + 2 * tl);
            unsigned bl1 = *(const unsigned*)(Bl + n * 24 + 8 + 2 * tl);
            mma16816(c1[nt], ah, bh0, bh1);
            mma16816(c1[nt], ah, bl0, bl1);
            mma16816(c1[nt], al, bh0, bh1);
        }
        __syncthreads();
    }

    // prefetch E tile 0 for GEMM2 (overlaps epilogue of GEMM1)
    ph0 = *(const uint4*)(g_Eth + tid * DD);
    ph1 = *(const uint4*)(g_Eth + tid * DD + 8);
    pl0 = *(const uint4*)(g_Etl + tid * DD);
    pl1 = *(const uint4*)(g_Etl + tid * DD + 8);

    // ---- gelu + hidden->A2 + dot partials ----
    float bdot = s_bd[0], os = s_bd[1];
    float dpA = 0.f, dpB = 0.f;
#pragma unroll
    for (int nt = 0; nt < 4; nt++) {
        int col = (warp * 4 + nt) * 8 + 2 * tl;
        float h0 = gelu(c1[nt][0] + b1_s[col]);
        float h1 = gelu(c1[nt][1] + b1_s[col + 1]);
        float h2 = gelu(c1[nt][2] + b1_s[col]);
        float h3 = gelu(c1[nt][3] + b1_s[col + 1]);
        dpA += h0 * u_s[col] + h1 * u_s[col + 1];
        dpB += h2 * u_s[col] + h3 * u_s[col + 1];
        __nv_bfloat16 e0, f0, e1, f1;
        bsplit(h0, e0, f0); bsplit(h1, e1, f1);
        *(unsigned*)(A2h + g * 264 + col) = bpack2(e0, e1);
        *(unsigned*)(A2l + g * 264 + col) = bpack2(f0, f1);
        bsplit(h2, e0, f0); bsplit(h3, e1, f1);
        *(unsigned*)(A2h + (g + 8) * 264 + col) = bpack2(e0, e1);
        *(unsigned*)(A2l + (g + 8) * 264 + col) = bpack2(f0, f1);
    }
    dpA += __shfl_xor_sync(0xffffffffu, dpA, 1);
    dpA += __shfl_xor_sync(0xffffffffu, dpA, 2);
    dpB += __shfl_xor_sync(0xffffffffu, dpB, 1);
    dpB += __shfl_xor_sync(0xffffffffu, dpB, 2);
    if (tl == 0) {
        redA[g * 8 + warp] = dpA;
        redA[(g + 8) * 8 + warp] = dpB;
    }
    __syncthreads();
    if (tid < MAXO) {
        float s = 0.f;
#pragma unroll
        for (int w = 0; w < 8; w++) s += redA[tid * 8 + w];
        dots[tid] = s + bdot;
    }

    // ============ GEMM2: hE = hidden @ E, K=256 (16 tiles) ============
    float c2[4][4];
#pragma unroll
    for (int nt = 0; nt < 4; nt++)
#pragma unroll
        for (int j = 0; j < 4; j++) c2[nt][j] = 0.f;

    for (int t = 0; t < 16; t++) {
        *(uint4*)(Bh + tid * 24) = ph0;
        *(uint4*)(Bh + tid * 24 + 8) = ph1;
        *(uint4*)(Bl + tid * 24) = pl0;
        *(uint4*)(Bl + tid * 24 + 8) = pl1;
        __syncthreads();
        if (t < 15) {
            int o = tid * DD + 16 * (t + 1);
            ph0 = *(const uint4*)(g_Eth + o);
            ph1 = *(const uint4*)(g_Eth + o + 8);
            pl0 = *(const uint4*)(g_Etl + o);
            pl1 = *(const uint4*)(g_Etl + o + 8);
        }
        unsigned ah[4], al[4];
        {
            int k0 = 16 * t + 2 * tl;
            ah[0] = *(const unsigned*)(A2h + g * 264 + k0);
            ah[1] = *(const unsigned*)(A2h + (g + 8) * 264 + k0);
            ah[2] = *(const unsigned*)(A2h + g * 264 + k0 + 8);
            ah[3] = *(const unsigned*)(A2h + (g + 8) * 264 + k0 + 8);
            al[0] = *(const unsigned*)(A2l + g * 264 + k0);
            al[1] = *(const unsigned*)(A2l + (g + 8) * 264 + k0);
            al[2] = *(const unsigned*)(A2l + g * 264 + k0 + 8);
            al[3] = *(const unsigned*)(A2l + (g + 8) * 264 + k0 + 8);
        }
#pragma unroll
        for (int nt = 0; nt < 4; nt++) {
            int n = (warp * 4 + nt) * 8 + g;
            unsigned bh0 = *(const unsigned*)(Bh + n * 24 + 2 * tl);
            unsigned bh1 = *(const unsigned*)(Bh + n * 24 + 8 + 2 * tl);
            unsigned bl0 = *(const unsigned*)(Bl + n * 24 + 2 * tl);
            unsigned bl1 = *(const unsigned*)(Bl + n * 24 + 8 + 2 * tl);
            mma16816(c2[nt], ah, bh0, bh1);
            mma16816(c2[nt], ah, bl0, bl1);
            mma16816(c2[nt], al, bh0, bh1);
        }
        __syncthreads();
    }

    // ---- epilogue: pre = os*(hE + r - dot*q) + bp ; invalid -> bp ----
    float prer[4][4];
    float dA = dots[g], dB = dots[g + 8];
    int vA = vld[g], vB = vld[g + 8];
#pragma unroll
    for (int nt = 0; nt < 4; nt++) {
        int col = (warp * 4 + nt) * 8 + 2 * tl;
        float r0v = r_s[col], r1v = r_s[col + 1];
        float q0 = q_s[col], q1 = q_s[col + 1];
        float bp0 = bp_s[col], bp1 = bp_s[col + 1];
        float p0 = os * (c2[nt][0] + r0v - dA * q0) + bp0;
        float p1 = os * (c2[nt][1] + r1v - dA * q1) + bp1;
        float p2 = os * (c2[nt][2] + r0v - dB * q0) + bp0;
        float p3 = os * (c2[nt][3] + r1v - dB * q1) + bp1;
        prer[nt][0] = vA ? p0 : bp0;
        prer[nt][1] = vA ? p1 : bp1;
        prer[nt][2] = vB ? p2 : bp0;
        prer[nt][3] = vB ? p3 : bp1;
    }

    // ---- layernorm ----
    float psA = 0.f, pqA = 0.f, psB = 0.f, pqB = 0.f;
#pragma unroll
    for (int nt = 0; nt < 4; nt++) {
        psA += prer[nt][0] + prer[nt][1];
        pqA += prer[nt][0] * prer[nt][0] + prer[nt][1] * prer[nt][1];
        psB += prer[nt][2] + prer[nt][3];
        pqB += prer[nt][2] * prer[nt][2] + prer[nt][3] * prer[nt][3];
    }
    psA += __shfl_xor_sync(0xffffffffu, psA, 1);
    psA += __shfl_xor_sync(0xffffffffu, psA, 2);
    pqA += __shfl_xor_sync(0xffffffffu, pqA, 1);
    pqA += __shfl_xor_sync(0xffffffffu, pqA, 2);
    psB += __shfl_xor_sync(0xffffffffu, psB, 1);
    psB += __shfl_xor_sync(0xffffffffu, psB, 2);
    pqB += __shfl_xor_sync(0xffffffffu, pqB, 1);
    pqB += __shfl_xor_sync(0xffffffffu, pqB, 2);
    if (tl == 0) {
        redA[g * 8 + warp] = psA;
        redA[(g + 8) * 8 + warp] = psB;
        redB[g * 8 + warp] = pqA;
        redB[(g + 8) * 8 + warp] = pqB;
    }
    __syncthreads();
    if (tid < MAXO) {
        float s = 0.f, sq = 0.f;
#pragma unroll
        for (int w = 0; w < 8; w++) { s += redA[tid * 8 + w]; sq += redB[tid * 8 + w]; }
        float m = s * (1.0f / DD);
        mur[tid] = m;
        float va = sq * (1.0f / DD) - m * m;
        rstd[tid] = rsqrtf(va + 1e-5f);
    }
    __syncthreads();

    float mA = mur[g], rsA = rstd[g], mB = mur[g + 8], rsB = rstd[g + 8];
#pragma unroll
    for (int nt = 0; nt < 4; nt++) {
        int col = (warp * 4 + nt) * 8 + 2 * tl;
        float g0 = gm_s[col], g1 = gm_s[col + 1];
        float t0 = bt_s[col], t1 = bt_s[col + 1];
        float2 o0, o1;
        o0.x = (prer[nt][0] - mA) * rsA * g0 + t0;
        o0.y = (prer[nt][1] - mA) * rsA * g1 + t1;
        o1.x = (prer[nt][2] - mB) * rsB * g0 + t0;
        o1.y = (prer[nt][3] - mB) * rsB * g1 + t1;
        *(float2*)&out[((size_t)(b * MAXO + g)) * DD + col] = o0;
        *(float2*)&out[((size_t)(b * MAXO + g + 8)) * DD + col] = o1;
    }
}

#define MLP_SMEM 68608

// =========================================================================
extern "C" void kernel_launch(void* const* d_in, const int* in_sizes, int n_in,
                              void* d_out, int out_size) {
    const float* grid_emb = (const float*)d_in[0];
    const int*   grid     = (const int*)d_in[1];
    const float* sr       = (const float*)d_in[2];
    const float* W1       = (const float*)d_in[3];
    const float* b1       = (const float*)d_in[4];
    const float* W2       = (const float*)d_in[5];
    const float* b2       = (const float*)d_in[6];
    const float* Wp       = (const float*)d_in[7];
    const float* bp       = (const float*)d_in[8];
    const float* gamma    = (const float*)d_in[9];
    const float* beta     = (const float*)d_in[10];
    const float* os       = (const float*)d_in[11];

    cudaFuncSetAttribute(mlp_kernel, cudaFuncAttributeMaxDynamicSharedMemorySize, MLP_SMEM);

    pre_kernel<<<PRE_GRID, 1024>>>(grid_emb, grid, sr, W1, W2, Wp, b2);
    mlp_kernel<<<BB, 256, MLP_SMEM>>>(b1, gamma, beta, bp, os, (float*)d_out);
}

// round 13
// speedup vs baseline: 1.6825x; 1.6528x over previous
#include <cuda_runtime.h>
#include <cuda_bf16.h>
#include <math.h>

#define HH 30
#define WWG 30
#define HW 900
#define DD 256
#define MAXO 16
#define BB 128
#define FPITCH 288   // 261 feature rows padded to 288 (18 K-tiles of 16)
#define CHUNK 1024
#define PF 8

// ---------------- device scratch ----------------
__device__ __align__(16) float g_comb[BB * FPITCH * MAXO];  // [b][feat][k]
__device__ __align__(16) float g_u[BB * DD];
__device__ __align__(16) float g_q[BB * DD];
__device__ float g_bdot[BB];
__device__ __align__(16) float g_r[DD];                     // b2 @ Wp
__device__ int   g_valid[BB * MAXO];
// fragment-shuffled bf16 weights: [(t*8+w)*32+lane][nt][b0lo,b0hi,b1lo,b1hi]
__device__ __align__(16) __nv_bfloat16 g_W1fh[18 * 8 * 32 * 16];
__device__ __align__(16) __nv_bfloat16 g_W1fl[18 * 8 * 32 * 16];
__device__ __align__(16) __nv_bfloat16 g_Efh[16 * 8 * 32 * 16];
__device__ __align__(16) __nv_bfloat16 g_Efl[16 * 8 * 32 * 16];

__device__ __forceinline__ void bsplit(float x, __nv_bfloat16& h, __nv_bfloat16& l) {
    h = __float2bfloat16(x);
    l = __float2bfloat16(x - __bfloat162float(h));
}
__device__ __forceinline__ unsigned bpack2(__nv_bfloat16 a, __nv_bfloat16 b) {
    return ((unsigned)__bfloat16_as_ushort(b) << 16) | __bfloat16_as_ushort(a);
}
__device__ __forceinline__ void mma16816(float c[4], const unsigned a[4],
                                         unsigned b0, unsigned b1) {
    asm volatile(
        "mma.sync.aligned.m16n8k16.row.col.f32.bf16.bf16.f32 "
        "{%0,%1,%2,%3},{%4,%5,%6,%7},{%8,%9},{%0,%1,%2,%3};"
        : "+f"(c[0]), "+f"(c[1]), "+f"(c[2]), "+f"(c[3])
        : "r"(a[0]), "r"(a[1]), "r"(a[2]), "r"(a[3]), "r"(b0), "r"(b1));
}
__device__ __forceinline__ float gelu(float x) {
    return 0.5f * x * (1.0f + erff(x * 0.70710678118654752f));
}
// weight element (k,n) -> fragment-shuffled bf16 index (validated mapping:
// inverse of the R11 fragment equations b0={k=2tl,2tl+1}@col n, b1={k=2tl+8,+9})
__device__ __forceinline__ size_t fragidx(int k, int n) {
    int t = k >> 4, kk = k & 15;
    int w = n >> 5, nt = (n >> 3) & 3, gq = n & 7;
    int bsel = kk >> 3, tl2 = (kk & 7) >> 1, half = kk & 1;
    int lane = gq * 4 + tl2;
    return ((((size_t)(t * 8 + w) * 32 + lane) * 4 + nt) * 4) + bsel * 2 + half;
}

// =========================================================================
// Fused pre-kernel, 1024 threads/block (R9-proven CCL/prep; W1/E branches
// emit fragment-shuffled bf16 hi/lo).
// blockIdx: [0,128) ccl, [128,256) prep, [256,288) E, 288 r, [289,307) W1.
// =========================================================================
__global__ __launch_bounds__(1024) void pre_kernel(const float* __restrict__ grid_emb,
                                                   const int* __restrict__ grid,
                                                   const float* __restrict__ sr,
                                                   const float* __restrict__ W1,
                                                   const float* __restrict__ W2,
                                                   const float* __restrict__ Wp,
                                                   const float* __restrict__ b2) {
    int br = blockIdx.x, tid = threadIdx.x;

    __shared__ __align__(16) char spool[46080];
    __shared__ unsigned rootbits[32];
    __shared__ int wpre[32];
    __shared__ int s_flag[2];
    __shared__ int nvalid;
    __shared__ int robj[MAXO], rmin[MAXO], rmax[MAXO], cmin[MAXO], cmax[MAXO];
    __shared__ int offs[MAXO + 1];

    if (br < BB) {
        int* g       = (int*)spool;
        int* lab     = g + HW;
        int* slot_of = lab + HW;
        float* fpool = (float*)(spool + 10816);
        int* ipool   = (int*)(spool + 27200);

        int b = br;
        for (int c = tid; c < HW; c += 1024) {
            int v = grid[b * HW + c];
            g[c] = v;
            lab[c] = (v > 0) ? c : HW;
            slot_of[c] = -1;
        }
        if (tid < 32) rootbits[tid] = 0;
        if (tid == 0) { s_flag[0] = 0; s_flag[1] = 0; }
        __syncthreads();

        for (int it = 0; it < 512; it++) {
            int f = it & 1;
            if (tid == 0) s_flag[1 - f] = 0;
            int changed = 0;
            for (int c = tid; c < HW; c += 1024) {
                int gc = g[c];
                if (gc > 0) {
                    int m = lab[c];
                    int col = c % WWG;
                    if (c >= WWG && g[c - WWG] == gc) { int t = lab[c - WWG]; if (t < m) m = t; }
                    if (c < HW - WWG && g[c + WWG] == gc) { int t = lab[c + WWG]; if (t < m) m = t; }
                    if (col > 0 && g[c - 1] == gc) { int t = lab[c - 1]; if (t < m) m = t; }
                    if (col < WWG - 1 && g[c + 1] == gc) { int t = lab[c + 1]; if (t < m) m = t; }
#pragma unroll
                    for (int hop = 0; hop < 8; hop++) {
                        int p = lab[m];
                        if (p >= m) break;
                        m = p;
                    }
                    if (m < lab[c]) { lab[c] = m; changed = 1; }
                }
            }
            if (changed) s_flag[f] = 1;
            __syncthreads();
            int chg = s_flag[f];
            __syncthreads();
            if (!chg) break;
        }

        for (int c = tid; c < HW; c += 1024)
            if (g[c] > 0 && lab[c] == c) atomicOr(&rootbits[c >> 5], 1u << (c & 31));
        __syncthreads();
        if (tid == 0) {
            int s = 0;
            for (int w = 0; w < 29; w++) { wpre[w] = s; s += __popc(rootbits[w]); }
            nvalid = s < MAXO ? s : MAXO;
        }
        __syncthreads();
        for (int c = tid; c < HW; c += 1024) {
            if (g[c] > 0 && lab[c] == c) {
                int w = c >> 5;
                int rank = wpre[w] + __popc(rootbits[w] & ((1u << (c & 31)) - 1u));
                if (rank < MAXO) { robj[rank] = c; slot_of[c] = rank; }
            }
        }
        if (tid < MAXO) { rmin[tid] = HH; rmax[tid] = -1; cmin[tid] = WWG; cmax[tid] = -1; }
        __syncthreads();
        for (int c = tid; c < HW; c += 1024) {
            if (g[c] > 0) {
                int s = slot_of[lab[c]];
                if (s >= 0) {
                    int r = c / WWG, col = c % WWG;
                    atomicMin(&rmin[s], r); atomicMax(&rmax[s], r);
                    atomicMin(&cmin[s], col); atomicMax(&cmax[s], col);
                }
            }
        }
        __syncthreads();

        int nv = nvalid;
        if (tid == 0) {
            int off = 0;
            for (int k = 0; k < nv; k++) {
                offs[k] = off;
                off += (rmax[k] + 1 - rmin[k]) * (cmax[k] + 1 - cmin[k]);
            }
            offs[nv] = off;
        }
        for (int i = tid; i < MAXO * DD; i += 1024) fpool[i] = 0.f;
        __syncthreads();

        int total = offs[nv];
        int ch = tid & 255, grp = tid >> 8;
        const float* gbase = grid_emb + (size_t)b * HW * DD + ch;
        for (int base = 0; base < total; base += CHUNK) {
            int n = min(CHUNK, total - base);
            for (int e = tid; e < n; e += 1024) {
                int ge = base + e;
                int k = 0;
                while (k + 1 < nv && ge >= offs[k + 1]) k++;
                int local = ge - offs[k];
                int bw = cmax[k] + 1 - cmin[k];
                int li = local / bw, lj = local - li * bw;
                int cell = (rmin[k] + li) * WWG + cmin[k] + lj;
                ipool[e] = (k << 16) | cell;
            }
            __syncthreads();
            int n4 = (n + 3) >> 2;
            int s0 = grp * n4, s1 = min(n, s0 + n4);
            float run = 0.f;
            int prev = -1;
            for (int e0b = s0; e0b < s1; e0b += PF) {
                int m = s1 - e0b; if (m > PF) m = PF;
                float v[PF]; int kk[PF];
#pragma unroll
                for (int j = 0; j < PF; j++) {
                    if (j < m) {
                        int ent = ipool[e0b + j];
                        kk[j] = ent >> 16;
                        v[j] = gbase[(size_t)(ent & 0xffff) * DD];
                    }
                }
#pragma unroll
                for (int j = 0; j < PF; j++) {
                    if (j < m) {
                        if (kk[j] != prev) {
                            if (prev >= 0) atomicAdd(&fpool[prev * DD + ch], run);
                            run = 0.f;
                            prev = kk[j];
                        }
                        run += v[j];
                    }
                }
            }
            if (prev >= 0) atomicAdd(&fpool[prev * DD + ch], run);
            __syncthreads();
        }

        float* cb = g_comb + (size_t)b * FPITCH * MAXO;
        for (int i = tid; i < FPITCH * MAXO; i += 1024) cb[i] = 0.f;
        if (tid < MAXO) g_valid[b * MAXO + tid] = (tid < nv) ? 1 : 0;
        __syncthreads();
        if (tid < DD) {
            for (int k = 0; k < nv; k++) {
                int y = rmin[k], x = cmin[k];
                int h = rmax[k] + 1 - y, w = cmax[k] + 1 - x;
                cb[tid * MAXO + k] = fpool[k * DD + tid] / (float)(h * w);
                if (tid < 5) {
                    float v;
                    int color = g[robj[k]];
                    if (tid == 0)      v = (float)color * (1.0f / 9.0f);
                    else if (tid == 1) v = (float)x * (1.0f / WWG);
                    else if (tid == 2) v = (float)y * (1.0f / HH);
                    else if (tid == 3) v = (float)w * (1.0f / WWG);
                    else               v = (float)h * (1.0f / HH);
                    cb[(DD + tid) * MAXO + k] = v;
                }
            }
        }
    } else if (br < 2 * BB) {
        // ---------------- prep: sn, u, q, bdot ----------------
        int b = br - BB;
        float* sn   = (float*)spool;
        float* sred = sn + DD;
        float s = 0.f;
        if (tid < DD) {
            const float* base = sr + (size_t)b * 8 * DD + tid;
#pragma unroll
            for (int j = 0; j < 8; j++) s += base[j * DD];
            s *= 0.125f;
            sred[tid] = s * s;
        }
        __syncthreads();
        for (int off = 128; off; off >>= 1) {
            if (tid < off) sred[tid] += sred[tid + off];
            __syncthreads();
        }
        float nrm = sqrtf(sred[0]);
        __syncthreads();
        float snv = s / fmaxf(nrm, 1e-8f);
        if (tid < DD) { sn[tid] = snv; sred[tid] = snv * b2[tid]; }
        __syncthreads();
        for (int off = 128; off; off >>= 1) {
            if (tid < off) sred[tid] += sred[tid + off];
            __syncthreads();
        }
        if (tid == 0) g_bdot[b] = sred[0];

        if (tid < DD) {
            float acc = 0.f;
#pragma unroll 8
            for (int d = 0; d < DD; d++) acc += sn[d] * Wp[d * DD + tid];
            g_q[b * DD + tid] = acc;
        }

        int wid = tid >> 5, lane = tid & 31;
        for (int d = wid; d < DD; d += 32) {
            float a = 0.f;
            const float* wr = W2 + d * DD;
#pragma unroll 4
            for (int e2 = lane; e2 < DD; e2 += 32) a += wr[e2] * sn[e2];
#pragma unroll
            for (int off = 16; off; off >>= 1) a += __shfl_down_sync(0xffffffffu, a, off);
            if (lane == 0) g_u[b * DD + d] = a;
        }
    } else if (br < 2 * BB + 32) {
        // ---- E rows -> fragment-shuffled bf16 hi/lo (E[k=d][n=e]) ----
        int d0 = (br - 2 * BB) * 8;
        int e = tid & 255, sub = tid >> 8;
        int r0 = sub * 2;
        float* wpt = (float*)spool;
        float* w2s = (float*)(spool + 32768);
        for (int i = tid; i < 8 * DD; i += 1024) w2s[i] = W2[d0 * DD + i];
        const float4* wp4 = (const float4*)Wp;
        float4 pf0 = wp4[tid], pf1 = wp4[tid + 1024];
        __syncthreads();
        float a0 = 0.f, a1 = 0.f;
        for (int t = 0; t < 8; t++) {
            ((float4*)wpt)[tid] = pf0;
            ((float4*)wpt)[tid + 1024] = pf1;
            __syncthreads();
            if (t < 7) {
                pf0 = wp4[(t + 1) * 2048 + tid];
                pf1 = wp4[(t + 1) * 2048 + tid + 1024];
            }
#pragma unroll 8
            for (int k = 0; k < 32; k++) {
                float wp = wpt[k * 256 + e];
                a0 += w2s[r0 * DD + t * 32 + k] * wp;
                a1 += w2s[(r0 + 1) * DD + t * 32 + k] * wp;
            }
            __syncthreads();
        }
        __nv_bfloat16 h, l;
        bsplit(a0, h, l);
        { size_t ix = fragidx(d0 + r0, e); g_Efh[ix] = h; g_Efl[ix] = l; }
        bsplit(a1, h, l);
        { size_t ix = fragidx(d0 + r0 + 1, e); g_Efh[ix] = h; g_Efl[ix] = l; }
    } else if (br == 2 * BB + 32) {
        if (tid < DD) {
            float a = 0.f;
#pragma unroll 8
            for (int k = 0; k < DD; k++) a += b2[k] * Wp[k * DD + tid];
            g_r[tid] = a;
        }
    } else {
        // ---- W1 (261x256, pad to 288) -> fragment-shuffled bf16 hi/lo ----
        int i = (br - (2 * BB + 33)) * 1024 + tid;   // float4 idx 0..18431
        if (i < (FPITCH * DD) / 4) {
            const float4* w14 = (const float4*)W1;   // 16704 real float4s
            float4 v = make_float4(0.f, 0.f, 0.f, 0.f);
            if (i < 16704) v = w14[i];
            int k = i >> 6;
            int n0 = (i & 63) * 4;
            float vals[4] = {v.x, v.y, v.z, v.w};
#pragma unroll
            for (int c = 0; c < 4; c++) {
                __nv_bfloat16 h, l;
                bsplit(vals[c], h, l);
                size_t ix = fragidx(k, n0 + c);
                g_W1fh[ix] = h;
                g_W1fl[ix] = l;
            }
        }
    }
}
#define PRE_GRID (2 * BB + 33 + 18)   // 307

// =========================================================================
// Tensor-core MLP v2: fragment-streamed weights (global->register, no B smem,
// no barriers in GEMM loops). One block = one batch (M=16), 8 warps.
// =========================================================================
__global__ __launch_bounds__(256) void mlp_kernel(const float* __restrict__ b1v,
                                                  const float* __restrict__ gv,
                                                  const float* __restrict__ btv,
                                                  const float* __restrict__ bpv,
                                                  const float* __restrict__ osp,
                                                  float* __restrict__ out) {
    int b = blockIdx.x, tid = threadIdx.x;
    int warp = tid >> 5, lane = tid & 31;
    int g = lane >> 2, tl = lane & 3;

    extern __shared__ char smraw[];
    __nv_bfloat16* A1h = (__nv_bfloat16*)(smraw);            // 16 x 296
    __nv_bfloat16* A1l = (__nv_bfloat16*)(smraw + 9472);
    __nv_bfloat16* A2h = (__nv_bfloat16*)(smraw + 18944);    // 16 x 264
    __nv_bfloat16* A2l = (__nv_bfloat16*)(smraw + 27392);
    float* u_s  = (float*)(smraw + 35840);
    float* q_s  = (float*)(smraw + 36864);
    float* r_s  = (float*)(smraw + 37888);
    float* bp_s = (float*)(smraw + 38912);
    float* gm_s = (float*)(smraw + 39936);
    float* bt_s = (float*)(smraw + 40960);
    float* b1_s = (float*)(smraw + 41984);
    float* redA = (float*)(smraw + 43008);   // [16][8]
    float* redB = (float*)(smraw + 43520);   // [16][8]
    __shared__ float dots[MAXO], mur[MAXO], rstd[MAXO], s_bd[2];
    __shared__ int vld[MAXO];

    // ---- stage A1 + constants ----
    const float* cbase = g_comb + (size_t)b * FPITCH * MAXO;
    for (int i = tid; i < FPITCH * MAXO; i += 256) {
        float x = cbase[i];
        int feat = i >> 4, obj = i & 15;
        __nv_bfloat16 h, l;
        bsplit(x, h, l);
        A1h[obj * 296 + feat] = h;
        A1l[obj * 296 + feat] = l;
    }
    u_s[tid] = g_u[b * DD + tid];
    q_s[tid] = g_q[b * DD + tid];
    r_s[tid] = g_r[tid];
    bp_s[tid] = bpv[tid];
    gm_s[tid] = gv[tid];
    bt_s[tid] = btv[tid];
    b1_s[tid] = b1v[tid];
    if (tid < MAXO) vld[tid] = g_valid[b * MAXO + tid];
    if (tid == 0) { s_bd[0] = g_bdot[b]; s_bd[1] = osp[0]; }

    const uint4* wfh = (const uint4*)g_W1fh;  // per tile: 512 uint4
    const uint4* wfl = (const uint4*)g_W1fl;
    const uint4* efh = (const uint4*)g_Efh;
    const uint4* efl = (const uint4*)g_Efl;
    int widx = (warp * 32 + lane) * 2;

    uint4 qh0 = wfh[widx], qh1 = wfh[widx + 1];
    uint4 ql0 = wfl[widx], ql1 = wfl[widx + 1];
    __syncthreads();

    // ============ GEMM1: hidden = gelu(A1 @ W1 + b1), 18 tiles, no barriers ============
    float c1[4][4];
#pragma unroll
    for (int nt = 0; nt < 4; nt++)
#pragma unroll
        for (int j = 0; j < 4; j++) c1[nt][j] = 0.f;

#pragma unroll 2
    for (int t = 0; t < 18; t++) {
        uint4 nh0, nh1, nl0, nl1;
        if (t < 17) {
            int o = widx + (t + 1) * 512;
            nh0 = wfh[o]; nh1 = wfh[o + 1];
            nl0 = wfl[o]; nl1 = wfl[o + 1];
        }
        unsigned ah[4], al[4];
        int k0 = 16 * t + 2 * tl;
        ah[0] = *(const unsigned*)(A1h + g * 296 + k0);
        ah[1] = *(const unsigned*)(A1h + (g + 8) * 296 + k0);
        ah[2] = *(const unsigned*)(A1h + g * 296 + k0 + 8);
        ah[3] = *(const unsigned*)(A1h + (g + 8) * 296 + k0 + 8);
        al[0] = *(const unsigned*)(A1l + g * 296 + k0);
        al[1] = *(const unsigned*)(A1l + (g + 8) * 296 + k0);
        al[2] = *(const unsigned*)(A1l + g * 296 + k0 + 8);
        al[3] = *(const unsigned*)(A1l + (g + 8) * 296 + k0 + 8);

        mma16816(c1[0], ah, qh0.x, qh0.y);
        mma16816(c1[0], al, qh0.x, qh0.y);
        mma16816(c1[0], ah, ql0.x, ql0.y);
        mma16816(c1[1], ah, qh0.z, qh0.w);
        mma16816(c1[1], al, qh0.z, qh0.w);
        mma16816(c1[1], ah, ql0.z, ql0.w);
        mma16816(c1[2], ah, qh1.x, qh1.y);
        mma16816(c1[2], al, qh1.x, qh1.y);
        mma16816(c1[2], ah, ql1.x, ql1.y);
        mma16816(c1[3], ah, qh1.z, qh1.w);
        mma16816(c1[3], al, qh1.z, qh1.w);
        mma16816(c1[3], ah, ql1.z, ql1.w);

        qh0 = nh0; qh1 = nh1; ql0 = nl0; ql1 = nl1;
    }

    // prefetch E tile 0
    qh0 = efh[widx]; qh1 = efh[widx + 1];
    ql0 = efl[widx]; ql1 = efl[widx + 1];

    // ---- gelu + hidden->A2 + dot partials ----
    float bdot = s_bd[0], os = s_bd[1];
    float dpA = 0.f, dpB = 0.f;
#pragma unroll
    for (int nt = 0; nt < 4; nt++) {
        int col = (warp * 4 + nt) * 8 + 2 * tl;
        float h0 = gelu(c1[nt][0] + b1_s[col]);
        float h1 = gelu(c1[nt][1] + b1_s[col + 1]);
        float h2 = gelu(c1[nt][2] + b1_s[col]);
        float h3 = gelu(c1[nt][3] + b1_s[col + 1]);
        dpA += h0 * u_s[col] + h1 * u_s[col + 1];
        dpB += h2 * u_s[col] + h3 * u_s[col + 1];
        __nv_bfloat16 e0, f0, e1, f1;
        bsplit(h0, e0, f0); bsplit(h1, e1, f1);
        *(unsigned*)(A2h + g * 264 + col) = bpack2(e0, e1);
        *(unsigned*)(A2l + g * 264 + col) = bpack2(f0, f1);
        bsplit(h2, e0, f0); bsplit(h3, e1, f1);
        *(unsigned*)(A2h + (g + 8) * 264 + col) = bpack2(e0, e1);
        *(unsigned*)(A2l + (g + 8) * 264 + col) = bpack2(f0, f1);
    }
    dpA += __shfl_xor_sync(0xffffffffu, dpA, 1);
    dpA += __shfl_xor_sync(0xffffffffu, dpA, 2);
    dpB += __shfl_xor_sync(0xffffffffu, dpB, 1);
    dpB += __shfl_xor_sync(0xffffffffu, dpB, 2);
    if (tl == 0) {
        redA[g * 8 + warp] = dpA;
        redA[(g + 8) * 8 + warp] = dpB;
    }
    __syncthreads();
    if (tid < MAXO) {
        float s = 0.f;
#pragma unroll
        for (int w = 0; w < 8; w++) s += redA[tid * 8 + w];
        dots[tid] = s + bdot;
    }

    // ============ GEMM2: hE = hidden @ E, 16 tiles, no barriers ============
    float c2[4][4];
#pragma unroll
    for (int nt = 0; nt < 4; nt++)
#pragma unroll
        for (int j = 0; j < 4; j++) c2[nt][j] = 0.f;

#pragma unroll 2
    for (int t = 0; t < 16; t++) {
        uint4 nh0, nh1, nl0, nl1;
        if (t < 15) {
            int o = widx + (t + 1) * 512;
            nh0 = efh[o]; nh1 = efh[o + 1];
            nl0 = efl[o]; nl1 = efl[o + 1];
        }
        unsigned ah[4], al[4];
        int k0 = 16 * t + 2 * tl;
        ah[0] = *(const unsigned*)(A2h + g * 264 + k0);
        ah[1] = *(const unsigned*)(A2h + (g + 8) * 264 + k0);
        ah[2] = *(const unsigned*)(A2h + g * 264 + k0 + 8);
        ah[3] = *(const unsigned*)(A2h + (g + 8) * 264 + k0 + 8);
        al[0] = *(const unsigned*)(A2l + g * 264 + k0);
        al[1] = *(const unsigned*)(A2l + (g + 8) * 264 + k0);
        al[2] = *(const unsigned*)(A2l + g * 264 + k0 + 8);
        al[3] = *(const unsigned*)(A2l + (g + 8) * 264 + k0 + 8);

        mma16816(c2[0], ah, qh0.x, qh0.y);
        mma16816(c2[0], al, qh0.x, qh0.y);
        mma16816(c2[0], ah, ql0.x, ql0.y);
        mma16816(c2[1], ah, qh0.z, qh0.w);
        mma16816(c2[1], al, qh0.z, qh0.w);
        mma16816(c2[1], ah, ql0.z, ql0.w);
        mma16816(c2[2], ah, qh1.x, qh1.y);
        mma16816(c2[2], al, qh1.x, qh1.y);
        mma16816(c2[2], ah, ql1.x, ql1.y);
        mma16816(c2[3], ah, qh1.z, qh1.w);
        mma16816(c2[3], al, qh1.z, qh1.w);
        mma16816(c2[3], ah, ql1.z, ql1.w);

        qh0 = nh0; qh1 = nh1; ql0 = nl0; ql1 = nl1;
    }
    __syncthreads();   // dots visible; A2 reads done

    // ---- epilogue: pre = os*(hE + r - dot*q) + bp ; invalid -> bp ----
    float prer[4][4];
    float dA = dots[g], dB = dots[g + 8];
    int vA = vld[g], vB = vld[g + 8];
#pragma unroll
    for (int nt = 0; nt < 4; nt++) {
        int col = (warp * 4 + nt) * 8 + 2 * tl;
        float r0v = r_s[col], r1v = r_s[col + 1];
        float q0 = q_s[col], q1 = q_s[col + 1];
        float bp0 = bp_s[col], bp1 = bp_s[col + 1];
        float p0 = os * (c2[nt][0] + r0v - dA * q0) + bp0;
        float p1 = os * (c2[nt][1] + r1v - dA * q1) + bp1;
        float p2 = os * (c2[nt][2] + r0v - dB * q0) + bp0;
        float p3 = os * (c2[nt][3] + r1v - dB * q1) + bp1;
        prer[nt][0] = vA ? p0 : bp0;
        prer[nt][1] = vA ? p1 : bp1;
        prer[nt][2] = vB ? p2 : bp0;
        prer[nt][3] = vB ? p3 : bp1;
    }

    // ---- layernorm ----
    float psA = 0.f, pqA = 0.f, psB = 0.f, pqB = 0.f;
#pragma unroll
    for (int nt = 0; nt < 4; nt++) {
        psA += prer[nt][0] + prer[nt][1];
        pqA += prer[nt][0] * prer[nt][0] + prer[nt][1] * prer[nt][1];
        psB += prer[nt][2] + prer[nt][3];
        pqB += prer[nt][2] * prer[nt][2] + prer[nt][3] * prer[nt][3];
    }
    psA += __shfl_xor_sync(0xffffffffu, psA, 1);
    psA += __shfl_xor_sync(0xffffffffu, psA, 2);
    pqA += __shfl_xor_sync(0xffffffffu, pqA, 1);
    pqA += __shfl_xor_sync(0xffffffffu, pqA, 2);
    psB += __shfl_xor_sync(0xffffffffu, psB, 1);
    psB += __shfl_xor_sync(0xffffffffu, psB, 2);
    pqB += __shfl_xor_sync(0xffffffffu, pqB, 1);
    pqB += __shfl_xor_sync(0xffffffffu, pqB, 2);
    if (tl == 0) {
        redA[g * 8 + warp] = psA;
        redA[(g + 8) * 8 + warp] = psB;
        redB[g * 8 + warp] = pqA;
        redB[(g + 8) * 8 + warp] = pqB;
    }
    __syncthreads();
    if (tid < MAXO) {
        float s = 0.f, sq = 0.f;
#pragma unroll
        for (int w = 0; w < 8; w++) { s += redA[tid * 8 + w]; sq += redB[tid * 8 + w]; }
        float m = s * (1.0f / DD);
        mur[tid] = m;
        float va = sq * (1.0f / DD) - m * m;
        rstd[tid] = rsqrtf(va + 1e-5f);
    }
    __syncthreads();

    float mA = mur[g], rsA = rstd[g], mB = mur[g + 8], rsB = rstd[g + 8];
#pragma unroll
    for (int nt = 0; nt < 4; nt++) {
        int col = (warp * 4 + nt) * 8 + 2 * tl;
        float g0 = gm_s[col], g1 = gm_s[col + 1];
        float t0 = bt_s[col], t1 = bt_s[col + 1];
        float2 o0, o1;
        o0.x = (prer[nt][0] - mA) * rsA * g0 + t0;
        o0.y = (prer[nt][1] - mA) * rsA * g1 + t1;
        o1.x = (prer[nt][2] - mB) * rsB * g0 + t0;
        o1.y = (prer[nt][3] - mB) * rsB * g1 + t1;
        *(float2*)&out[((size_t)(b * MAXO + g)) * DD + col] = o0;
        *(float2*)&out[((size_t)(b * MAXO + g + 8)) * DD + col] = o1;
    }
}

#define MLP_SMEM 44032

// =========================================================================
extern "C" void kernel_launch(void* const* d_in, const int* in_sizes, int n_in,
                              void* d_out, int out_size) {
    const float* grid_emb = (const float*)d_in[0];
    const int*   grid     = (const int*)d_in[1];
    const float* sr       = (const float*)d_in[2];
    const float* W1       = (const float*)d_in[3];
    const float* b1       = (const float*)d_in[4];
    const float* W2       = (const float*)d_in[5];
    const float* b2       = (const float*)d_in[6];
    const float* Wp       = (const float*)d_in[7];
    const float* bp       = (const float*)d_in[8];
    const float* gamma    = (const float*)d_in[9];
    const float* beta     = (const float*)d_in[10];
    const float* os       = (const float*)d_in[11];

    cudaFuncSetAttribute(mlp_kernel, cudaFuncAttributeMaxDynamicSharedMemorySize, MLP_SMEM);

    pre_kernel<<<PRE_GRID, 1024>>>(grid_emb, grid, sr, W1, W2, Wp, b2);
    mlp_kernel<<<BB, 256, MLP_SMEM>>>(b1, gamma, beta, bp, os, (float*)d_out);
}

// round 14
// speedup vs baseline: 1.6886x; 1.0036x over previous
#include <cuda_runtime.h>
#include <cuda_bf16.h>
#include <math.h>

#define HH 30
#define WWG 30
#define HW 900
#define DD 256
#define MAXO 16
#define BB 128
#define FPITCH 288   // 261 feature rows padded to 288 (18 K-tiles of 16)
#define CHUNK 1024
#define PF 8

// ---------------- device scratch ----------------
__device__ __align__(16) float g_comb[BB * FPITCH * MAXO];  // [b][feat][k]
__device__ __align__(16) float g_u[BB * DD];
__device__ __align__(16) float g_q[BB * DD];
__device__ float g_bdot[BB];
__device__ __align__(16) float g_r[DD];                     // b2 @ Wp
__device__ int   g_valid[BB * MAXO];
// interleaved fragment-shuffled bf16 weights:
// [(t*8+w)*32+lane] -> 32 bf16 = [qh0(8) | qh1(8) | ql0(8) | ql1(8)]
__device__ __align__(16) __nv_bfloat16 g_W1f[18 * 8 * 32 * 32];
__device__ __align__(16) __nv_bfloat16 g_Ef[16 * 8 * 32 * 32];

__device__ __forceinline__ void bsplit(float x, __nv_bfloat16& h, __nv_bfloat16& l) {
    h = __float2bfloat16(x);
    l = __float2bfloat16(x - __bfloat162float(h));
}
__device__ __forceinline__ unsigned bpack2(__nv_bfloat16 a, __nv_bfloat16 b) {
    return ((unsigned)__bfloat16_as_ushort(b) << 16) | __bfloat16_as_ushort(a);
}
__device__ __forceinline__ void mma16816(float c[4], const unsigned a[4],
                                         unsigned b0, unsigned b1) {
    asm volatile(
        "mma.sync.aligned.m16n8k16.row.col.f32.bf16.bf16.f32 "
        "{%0,%1,%2,%3},{%4,%5,%6,%7},{%8,%9},{%0,%1,%2,%3};"
        : "+f"(c[0]), "+f"(c[1]), "+f"(c[2]), "+f"(c[3])
        : "r"(a[0]), "r"(a[1]), "r"(a[2]), "r"(a[3]), "r"(b0), "r"(b1));
}
__device__ __forceinline__ float gelu(float x) {
    return 0.5f * x * (1.0f + erff(x * 0.70710678118654752f));
}
// weight element (k,n,islo) -> interleaved fragment index (bf16 units)
__device__ __forceinline__ size_t fragidx2(int k, int n, int islo) {
    int t = k >> 4, kk = k & 15;
    int w = n >> 5, nt = (n >> 3) & 3, gq = n & 7;
    int bsel = kk >> 3, tl2 = (kk & 7) >> 1, half = kk & 1;
    int lane = gq * 4 + tl2;
    int sub = islo * 16 + (nt >> 1) * 8 + (nt & 1) * 4 + bsel * 2 + half;
    return (((size_t)(t * 8 + w) * 32 + lane) * 32) + sub;
}

// =========================================================================
// Fused pre-kernel, 1024 threads/block (R13-proven; W1/E branches write the
// interleaved layout).
// blockIdx: [0,128) ccl, [128,256) prep, [256,288) E, 288 r, [289,307) W1.
// =========================================================================
__global__ __launch_bounds__(1024) void pre_kernel(const float* __restrict__ grid_emb,
                                                   const int* __restrict__ grid,
                                                   const float* __restrict__ sr,
                                                   const float* __restrict__ W1,
                                                   const float* __restrict__ W2,
                                                   const float* __restrict__ Wp,
                                                   const float* __restrict__ b2) {
    int br = blockIdx.x, tid = threadIdx.x;

    __shared__ __align__(16) char spool[46080];
    __shared__ unsigned rootbits[32];
    __shared__ int wpre[32];
    __shared__ int s_flag[2];
    __shared__ int nvalid;
    __shared__ int robj[MAXO], rmin[MAXO], rmax[MAXO], cmin[MAXO], cmax[MAXO];
    __shared__ int offs[MAXO + 1];

    if (br < BB) {
        int* g       = (int*)spool;
        int* lab     = g + HW;
        int* slot_of = lab + HW;
        float* fpool = (float*)(spool + 10816);
        int* ipool   = (int*)(spool + 27200);

        int b = br;
        for (int c = tid; c < HW; c += 1024) {
            int v = grid[b * HW + c];
            g[c] = v;
            lab[c] = (v > 0) ? c : HW;
            slot_of[c] = -1;
        }
        if (tid < 32) rootbits[tid] = 0;
        if (tid == 0) { s_flag[0] = 0; s_flag[1] = 0; }
        __syncthreads();

        for (int it = 0; it < 512; it++) {
            int f = it & 1;
            if (tid == 0) s_flag[1 - f] = 0;
            int changed = 0;
            for (int c = tid; c < HW; c += 1024) {
                int gc = g[c];
                if (gc > 0) {
                    int m = lab[c];
                    int col = c % WWG;
                    if (c >= WWG && g[c - WWG] == gc) { int t = lab[c - WWG]; if (t < m) m = t; }
                    if (c < HW - WWG && g[c + WWG] == gc) { int t = lab[c + WWG]; if (t < m) m = t; }
                    if (col > 0 && g[c - 1] == gc) { int t = lab[c - 1]; if (t < m) m = t; }
                    if (col < WWG - 1 && g[c + 1] == gc) { int t = lab[c + 1]; if (t < m) m = t; }
#pragma unroll
                    for (int hop = 0; hop < 8; hop++) {
                        int p = lab[m];
                        if (p >= m) break;
                        m = p;
                    }
                    if (m < lab[c]) { lab[c] = m; changed = 1; }
                }
            }
            if (changed) s_flag[f] = 1;
            __syncthreads();
            int chg = s_flag[f];
            __syncthreads();
            if (!chg) break;
        }

        for (int c = tid; c < HW; c += 1024)
            if (g[c] > 0 && lab[c] == c) atomicOr(&rootbits[c >> 5], 1u << (c & 31));
        __syncthreads();
        if (tid == 0) {
            int s = 0;
            for (int w = 0; w < 29; w++) { wpre[w] = s; s += __popc(rootbits[w]); }
            nvalid = s < MAXO ? s : MAXO;
        }
        __syncthreads();
        for (int c = tid; c < HW; c += 1024) {
            if (g[c] > 0 && lab[c] == c) {
                int w = c >> 5;
                int rank = wpre[w] + __popc(rootbits[w] & ((1u << (c & 31)) - 1u));
                if (rank < MAXO) { robj[rank] = c; slot_of[c] = rank; }
            }
        }
        if (tid < MAXO) { rmin[tid] = HH; rmax[tid] = -1; cmin[tid] = WWG; cmax[tid] = -1; }
        __syncthreads();
        for (int c = tid; c < HW; c += 1024) {
            if (g[c] > 0) {
                int s = slot_of[lab[c]];
                if (s >= 0) {
                    int r = c / WWG, col = c % WWG;
                    atomicMin(&rmin[s], r); atomicMax(&rmax[s], r);
                    atomicMin(&cmin[s], col); atomicMax(&cmax[s], col);
                }
            }
        }
        __syncthreads();

        int nv = nvalid;
        if (tid == 0) {
            int off = 0;
            for (int k = 0; k < nv; k++) {
                offs[k] = off;
                off += (rmax[k] + 1 - rmin[k]) * (cmax[k] + 1 - cmin[k]);
            }
            offs[nv] = off;
        }
        for (int i = tid; i < MAXO * DD; i += 1024) fpool[i] = 0.f;
        __syncthreads();

        int total = offs[nv];
        int ch = tid & 255, grp = tid >> 8;
        const float* gbase = grid_emb + (size_t)b * HW * DD + ch;
        for (int base = 0; base < total; base += CHUNK) {
            int n = min(CHUNK, total - base);
            for (int e = tid; e < n; e += 1024) {
                int ge = base + e;
                int k = 0;
                while (k + 1 < nv && ge >= offs[k + 1]) k++;
                int local = ge - offs[k];
                int bw = cmax[k] + 1 - cmin[k];
                int li = local / bw, lj = local - li * bw;
                int cell = (rmin[k] + li) * WWG + cmin[k] + lj;
                ipool[e] = (k << 16) | cell;
            }
            __syncthreads();
            int n4 = (n + 3) >> 2;
            int s0 = grp * n4, s1 = min(n, s0 + n4);
            float run = 0.f;
            int prev = -1;
            for (int e0b = s0; e0b < s1; e0b += PF) {
                int m = s1 - e0b; if (m > PF) m = PF;
                float v[PF]; int kk[PF];
#pragma unroll
                for (int j = 0; j < PF; j++) {
                    if (j < m) {
                        int ent = ipool[e0b + j];
                        kk[j] = ent >> 16;
                        v[j] = gbase[(size_t)(ent & 0xffff) * DD];
                    }
                }
#pragma unroll
                for (int j = 0; j < PF; j++) {
                    if (j < m) {
                        if (kk[j] != prev) {
                            if (prev >= 0) atomicAdd(&fpool[prev * DD + ch], run);
                            run = 0.f;
                            prev = kk[j];
                        }
                        run += v[j];
                    }
                }
            }
            if (prev >= 0) atomicAdd(&fpool[prev * DD + ch], run);
            __syncthreads();
        }

        float* cb = g_comb + (size_t)b * FPITCH * MAXO;
        for (int i = tid; i < FPITCH * MAXO; i += 1024) cb[i] = 0.f;
        if (tid < MAXO) g_valid[b * MAXO + tid] = (tid < nv) ? 1 : 0;
        __syncthreads();
        if (tid < DD) {
            for (int k = 0; k < nv; k++) {
                int y = rmin[k], x = cmin[k];
                int h = rmax[k] + 1 - y, w = cmax[k] + 1 - x;
                cb[tid * MAXO + k] = fpool[k * DD + tid] / (float)(h * w);
                if (tid < 5) {
                    float v;
                    int color = g[robj[k]];
                    if (tid == 0)      v = (float)color * (1.0f / 9.0f);
                    else if (tid == 1) v = (float)x * (1.0f / WWG);
                    else if (tid == 2) v = (float)y * (1.0f / HH);
                    else if (tid == 3) v = (float)w * (1.0f / WWG);
                    else               v = (float)h * (1.0f / HH);
                    cb[(DD + tid) * MAXO + k] = v;
                }
            }
        }
    } else if (br < 2 * BB) {
        // ---------------- prep: sn, u, q, bdot ----------------
        int b = br - BB;
        float* sn   = (float*)spool;
        float* sred = sn + DD;
        float s = 0.f;
        if (tid < DD) {
            const float* base = sr + (size_t)b * 8 * DD + tid;
#pragma unroll
            for (int j = 0; j < 8; j++) s += base[j * DD];
            s *= 0.125f;
            sred[tid] = s * s;
        }
        __syncthreads();
        for (int off = 128; off; off >>= 1) {
            if (tid < off) sred[tid] += sred[tid + off];
            __syncthreads();
        }
        float nrm = sqrtf(sred[0]);
        __syncthreads();
        float snv = s / fmaxf(nrm, 1e-8f);
        if (tid < DD) { sn[tid] = snv; sred[tid] = snv * b2[tid]; }
        __syncthreads();
        for (int off = 128; off; off >>= 1) {
            if (tid < off) sred[tid] += sred[tid + off];
            __syncthreads();
        }
        if (tid == 0) g_bdot[b] = sred[0];

        if (tid < DD) {
            float acc = 0.f;
#pragma unroll 8
            for (int d = 0; d < DD; d++) acc += sn[d] * Wp[d * DD + tid];
            g_q[b * DD + tid] = acc;
        }

        int wid = tid >> 5, lane = tid & 31;
        for (int d = wid; d < DD; d += 32) {
            float a = 0.f;
            const float* wr = W2 + d * DD;
#pragma unroll 4
            for (int e2 = lane; e2 < DD; e2 += 32) a += wr[e2] * sn[e2];
#pragma unroll
            for (int off = 16; off; off >>= 1) a += __shfl_down_sync(0xffffffffu, a, off);
            if (lane == 0) g_u[b * DD + d] = a;
        }
    } else if (br < 2 * BB + 32) {
        // ---- E rows -> interleaved fragment bf16 (E[k=d][n=e]) ----
        int d0 = (br - 2 * BB) * 8;
        int e = tid & 255, sub = tid >> 8;
        int r0 = sub * 2;
        float* wpt = (float*)spool;
        float* w2s = (float*)(spool + 32768);
        for (int i = tid; i < 8 * DD; i += 1024) w2s[i] = W2[d0 * DD + i];
        const float4* wp4 = (const float4*)Wp;
        float4 pf0 = wp4[tid], pf1 = wp4[tid + 1024];
        __syncthreads();
        float a0 = 0.f, a1 = 0.f;
        for (int t = 0; t < 8; t++) {
            ((float4*)wpt)[tid] = pf0;
            ((float4*)wpt)[tid + 1024] = pf1;
            __syncthreads();
            if (t < 7) {
                pf0 = wp4[(t + 1) * 2048 + tid];
                pf1 = wp4[(t + 1) * 2048 + tid + 1024];
            }
#pragma unroll 8
            for (int k = 0; k < 32; k++) {
                float wp = wpt[k * 256 + e];
                a0 += w2s[r0 * DD + t * 32 + k] * wp;
                a1 += w2s[(r0 + 1) * DD + t * 32 + k] * wp;
            }
            __syncthreads();
        }
        __nv_bfloat16 h, l;
        bsplit(a0, h, l);
        g_Ef[fragidx2(d0 + r0, e, 0)] = h;
        g_Ef[fragidx2(d0 + r0, e, 1)] = l;
        bsplit(a1, h, l);
        g_Ef[fragidx2(d0 + r0 + 1, e, 0)] = h;
        g_Ef[fragidx2(d0 + r0 + 1, e, 1)] = l;
    } else if (br == 2 * BB + 32) {
        if (tid < DD) {
            float a = 0.f;
#pragma unroll 8
            for (int k = 0; k < DD; k++) a += b2[k] * Wp[k * DD + tid];
            g_r[tid] = a;
        }
    } else {
        // ---- W1 (261x256, pad to 288) -> interleaved fragment bf16 ----
        int i = (br - (2 * BB + 33)) * 1024 + tid;   // float4 idx 0..18431
        if (i < (FPITCH * DD) / 4) {
            const float4* w14 = (const float4*)W1;   // 16704 real float4s
            float4 v = make_float4(0.f, 0.f, 0.f, 0.f);
            if (i < 16704) v = w14[i];
            int k = i >> 6;
            int n0 = (i & 63) * 4;
            float vals[4] = {v.x, v.y, v.z, v.w};
#pragma unroll
            for (int c = 0; c < 4; c++) {
                __nv_bfloat16 h, l;
                bsplit(vals[c], h, l);
                g_W1f[fragidx2(k, n0 + c, 0)] = h;
                g_W1f[fragidx2(k, n0 + c, 1)] = l;
            }
        }
    }
}
#define PRE_GRID (2 * BB + 33 + 18)   // 307

// per-thread 64B weight block load (4 x LDG.128 at immediate offsets)
#define LOADW(dst, arr, t, warp, lane)                                      \
    {                                                                       \
        const uint4* _p = (arr) + (((size_t)(t) * 8 + (warp)) * 32 + (lane)) * 4; \
        (dst)[0] = _p[0]; (dst)[1] = _p[1]; (dst)[2] = _p[2]; (dst)[3] = _p[3];   \
    }

// =========================================================================
// Tensor-core MLP v3: interleaved fragment-streamed weights, depth-2
// software pipeline, no barriers in GEMM loops. One block = one batch.
// =========================================================================
__global__ __launch_bounds__(256) void mlp_kernel(const float* __restrict__ b1v,
                                                  const float* __restrict__ gv,
                                                  const float* __restrict__ btv,
                                                  const float* __restrict__ bpv,
                                                  const float* __restrict__ osp,
                                                  float* __restrict__ out) {
    int b = blockIdx.x, tid = threadIdx.x;
    int warp = tid >> 5, lane = tid & 31;
    int g = lane >> 2, tl = lane & 3;

    extern __shared__ char smraw[];
    __nv_bfloat16* A1h = (__nv_bfloat16*)(smraw);            // 16 x 296
    __nv_bfloat16* A1l = (__nv_bfloat16*)(smraw + 9472);
    __nv_bfloat16* A2h = (__nv_bfloat16*)(smraw + 18944);    // 16 x 264
    __nv_bfloat16* A2l = (__nv_bfloat16*)(smraw + 27392);
    float* u_s  = (float*)(smraw + 35840);
    float* q_s  = (float*)(smraw + 36864);
    float* r_s  = (float*)(smraw + 37888);
    float* bp_s = (float*)(smraw + 38912);
    float* gm_s = (float*)(smraw + 39936);
    float* bt_s = (float*)(smraw + 40960);
    float* b1_s = (float*)(smraw + 41984);
    float* redA = (float*)(smraw + 43008);   // [16][8]
    float* redB = (float*)(smraw + 43520);   // [16][8]
    __shared__ float dots[MAXO], mur[MAXO], rstd[MAXO], s_bd[2];
    __shared__ int vld[MAXO];

    const uint4* wf = (const uint4*)g_W1f;
    const uint4* ef = (const uint4*)g_Ef;

    // pipeline prologue for GEMM1 (issue before A1 staging to hide latency)
    uint4 buf[2][4];
    LOADW(buf[0], wf, 0, warp, lane);
    LOADW(buf[1], wf, 1, warp, lane);

    // ---- stage A1 + constants ----
    const float* cbase = g_comb + (size_t)b * FPITCH * MAXO;
    for (int i = tid; i < FPITCH * MAXO; i += 256) {
        float x = cbase[i];
        int feat = i >> 4, obj = i & 15;
        __nv_bfloat16 h, l;
        bsplit(x, h, l);
        A1h[obj * 296 + feat] = h;
        A1l[obj * 296 + feat] = l;
    }
    u_s[tid] = g_u[b * DD + tid];
    q_s[tid] = g_q[b * DD + tid];
    r_s[tid] = g_r[tid];
    bp_s[tid] = bpv[tid];
    gm_s[tid] = gv[tid];
    bt_s[tid] = btv[tid];
    b1_s[tid] = b1v[tid];
    if (tid < MAXO) vld[tid] = g_valid[b * MAXO + tid];
    if (tid == 0) { s_bd[0] = g_bdot[b]; s_bd[1] = osp[0]; }
    __syncthreads();

    // ============ GEMM1: hidden = gelu(A1 @ W1 + b1), 18 tiles ============
    float c1[4][4];
#pragma unroll
    for (int nt = 0; nt < 4; nt++)
#pragma unroll
        for (int j = 0; j < 4; j++) c1[nt][j] = 0.f;

#pragma unroll
    for (int t = 0; t < 18; t++) {
        uint4 q0 = buf[t & 1][0], q1 = buf[t & 1][1];
        uint4 q2 = buf[t & 1][2], q3 = buf[t & 1][3];
        if (t + 2 < 18) LOADW(buf[t & 1], wf, t + 2, warp, lane);

        unsigned ah[4], al[4];
        int k0 = 16 * t + 2 * tl;
        ah[0] = *(const unsigned*)(A1h + g * 296 + k0);
        ah[1] = *(const unsigned*)(A1h + (g + 8) * 296 + k0);
        ah[2] = *(const unsigned*)(A1h + g * 296 + k0 + 8);
        ah[3] = *(const unsigned*)(A1h + (g + 8) * 296 + k0 + 8);
        al[0] = *(const unsigned*)(A1l + g * 296 + k0);
        al[1] = *(const unsigned*)(A1l + (g + 8) * 296 + k0);
        al[2] = *(const unsigned*)(A1l + g * 296 + k0 + 8);
        al[3] = *(const unsigned*)(A1l + (g + 8) * 296 + k0 + 8);

        mma16816(c1[0], ah, q0.x, q0.y);
        mma16816(c1[0], al, q0.x, q0.y);
        mma16816(c1[0], ah, q2.x, q2.y);
        mma16816(c1[1], ah, q0.z, q0.w);
        mma16816(c1[1], al, q0.z, q0.w);
        mma16816(c1[1], ah, q2.z, q2.w);
        mma16816(c1[2], ah, q1.x, q1.y);
        mma16816(c1[2], al, q1.x, q1.y);
        mma16816(c1[2], ah, q3.x, q3.y);
        mma16816(c1[3], ah, q1.z, q1.w);
        mma16816(c1[3], al, q1.z, q1.w);
        mma16816(c1[3], ah, q3.z, q3.w);
    }

    // GEMM2 pipeline prologue (hidden by gelu/dot epilogue below)
    LOADW(buf[0], ef, 0, warp, lane);
    LOADW(buf[1], ef, 1, warp, lane);

    // ---- gelu + hidden->A2 + dot partials ----
    float bdot = s_bd[0], os = s_bd[1];
    float dpA = 0.f, dpB = 0.f;
#pragma unroll
    for (int nt = 0; nt < 4; nt++) {
        int col = (warp * 4 + nt) * 8 + 2 * tl;
        float h0 = gelu(c1[nt][0] + b1_s[col]);
        float h1 = gelu(c1[nt][1] + b1_s[col + 1]);
        float h2 = gelu(c1[nt][2] + b1_s[col]);
        float h3 = gelu(c1[nt][3] + b1_s[col + 1]);
        dpA += h0 * u_s[col] + h1 * u_s[col + 1];
        dpB += h2 * u_s[col] + h3 * u_s[col + 1];
        __nv_bfloat16 e0, f0, e1, f1;
        bsplit(h0, e0, f0); bsplit(h1, e1, f1);
        *(unsigned*)(A2h + g * 264 + col) = bpack2(e0, e1);
        *(unsigned*)(A2l + g * 264 + col) = bpack2(f0, f1);
        bsplit(h2, e0, f0); bsplit(h3, e1, f1);
        *(unsigned*)(A2h + (g + 8) * 264 + col) = bpack2(e0, e1);
        *(unsigned*)(A2l + (g + 8) * 264 + col) = bpack2(f0, f1);
    }
    dpA += __shfl_xor_sync(0xffffffffu, dpA, 1);
    dpA += __shfl_xor_sync(0xffffffffu, dpA, 2);
    dpB += __shfl_xor_sync(0xffffffffu, dpB, 1);
    dpB += __shfl_xor_sync(0xffffffffu, dpB, 2);
    if (tl == 0) {
        redA[g * 8 + warp] = dpA;
        redA[(g + 8) * 8 + warp] = dpB;
    }
    __syncthreads();
    if (tid < MAXO) {
        float s = 0.f;
#pragma unroll
        for (int w = 0; w < 8; w++) s += redA[tid * 8 + w];
        dots[tid] = s + bdot;
    }

    // ============ GEMM2: hE = hidden @ E, 16 tiles ============
    float c2[4][4];
#pragma unroll
    for (int nt = 0; nt < 4; nt++)
#pragma unroll
        for (int j = 0; j < 4; j++) c2[nt][j] = 0.f;

#pragma unroll
    for (int t = 0; t < 16; t++) {
        uint4 q0 = buf[t & 1][0], q1 = buf[t & 1][1];
        uint4 q2 = buf[t & 1][2], q3 = buf[t & 1][3];
        if (t + 2 < 16) LOADW(buf[t & 1], ef, t + 2, warp, lane);

        unsigned ah[4], al[4];
        int k0 = 16 * t + 2 * tl;
        ah[0] = *(const unsigned*)(A2h + g * 264 + k0);
        ah[1] = *(const unsigned*)(A2h + (g + 8) * 264 + k0);
        ah[2] = *(const unsigned*)(A2h + g * 264 + k0 + 8);
        ah[3] = *(const unsigned*)(A2h + (g + 8) * 264 + k0 + 8);
        al[0] = *(const unsigned*)(A2l + g * 264 + k0);
        al[1] = *(const unsigned*)(A2l + (g + 8) * 264 + k0);
        al[2] = *(const unsigned*)(A2l + g * 264 + k0 + 8);
        al[3] = *(const unsigned*)(A2l + (g + 8) * 264 + k0 + 8);

        mma16816(c2[0], ah, q0.x, q0.y);
        mma16816(c2[0], al, q0.x, q0.y);
        mma16816(c2[0], ah, q2.x, q2.y);
        mma16816(c2[1], ah, q0.z, q0.w);
        mma16816(c2[1], al, q0.z, q0.w);
        mma16816(c2[1], ah, q2.z, q2.w);
        mma16816(c2[2], ah, q1.x, q1.y);
        mma16816(c2[2], al, q1.x, q1.y);
        mma16816(c2[2], ah, q3.x, q3.y);
        mma16816(c2[3], ah, q1.z, q1.w);
        mma16816(c2[3], al, q1.z, q1.w);
        mma16816(c2[3], ah, q3.z, q3.w);
    }
    __syncthreads();   // dots visible; A2 reads done

    // ---- epilogue: pre = os*(hE + r - dot*q) + bp ; invalid -> bp ----
    float prer[4][4];
    float dA = dots[g], dB = dots[g + 8];
    int vA = vld[g], vB = vld[g + 8];
#pragma unroll
    for (int nt = 0; nt < 4; nt++) {
        int col = (warp * 4 + nt) * 8 + 2 * tl;
        float r0v = r_s[col], r1v = r_s[col + 1];
        float q0 = q_s[col], q1 = q_s[col + 1];
        float bp0 = bp_s[col], bp1 = bp_s[col + 1];
        float p0 = os * (c2[nt][0] + r0v - dA * q0) + bp0;
        float p1 = os * (c2[nt][1] + r1v - dA * q1) + bp1;
        float p2 = os * (c2[nt][2] + r0v - dB * q0) + bp0;
        float p3 = os * (c2[nt][3] + r1v - dB * q1) + bp1;
        prer[nt][0] = vA ? p0 : bp0;
        prer[nt][1] = vA ? p1 : bp1;
        prer[nt][2] = vB ? p2 : bp0;
        prer[nt][3] = vB ? p3 : bp1;
    }

    // ---- layernorm ----
    float psA = 0.f, pqA = 0.f, psB = 0.f, pqB = 0.f;
#pragma unroll
    for (int nt = 0; nt < 4; nt++) {
        psA += prer[nt][0] + prer[nt][1];
        pqA += prer[nt][0] * prer[nt][0] + prer[nt][1] * prer[nt][1];
        psB += prer[nt][2] + prer[nt][3];
        pqB += prer[nt][2] * prer[nt][2] + prer[nt][3] * prer[nt][3];
    }
    psA += __shfl_xor_sync(0xffffffffu, psA, 1);
    psA += __shfl_xor_sync(0xffffffffu, psA, 2);
    pqA += __shfl_xor_sync(0xffffffffu, pqA, 1);
    pqA += __shfl_xor_sync(0xffffffffu, pqA, 2);
    psB += __shfl_xor_sync(0xffffffffu, psB, 1);
    psB += __shfl_xor_sync(0xffffffffu, psB, 2);
    pqB += __shfl_xor_sync(0xffffffffu, pqB, 1);
    pqB += __shfl_xor_sync(0xffffffffu, pqB, 2);
    if (tl == 0) {
        redA[g * 8 + warp] = psA;
        redA[(g + 8) * 8 + warp] = psB;
        redB[g * 8 + warp] = pqA;
        redB[(g + 8) * 8 + warp] = pqB;
    }
    __syncthreads();
    if (tid < MAXO) {
        float s = 0.f, sq = 0.f;
#pragma unroll
        for (int w = 0; w < 8; w++) { s += redA[tid * 8 + w]; sq += redB[tid * 8 + w]; }
        float m = s * (1.0f / DD);
        mur[tid] = m;
        float va = sq * (1.0f / DD) - m * m;
        rstd[tid] = rsqrtf(va + 1e-5f);
    }
    __syncthreads();

    float mA = mur[g], rsA = rstd[g], mB = mur[g + 8], rsB = rstd[g + 8];
#pragma unroll
    for (int nt = 0; nt < 4; nt++) {
        int col = (warp * 4 + nt) * 8 + 2 * tl;
        float g0 = gm_s[col], g1 = gm_s[col + 1];
        float t0 = bt_s[col], t1 = bt_s[col + 1];
        float2 o0, o1;
        o0.x = (prer[nt][0] - mA) * rsA * g0 + t0;
        o0.y = (prer[nt][1] - mA) * rsA * g1 + t1;
        o1.x = (prer[nt][2] - mB) * rsB * g0 + t0;
        o1.y = (prer[nt][3] - mB) * rsB * g1 + t1;
        *(float2*)&out[((size_t)(b * MAXO + g)) * DD + col] = o0;
        *(float2*)&out[((size_t)(b * MAXO + g + 8)) * DD + col] = o1;
    }
}

#define MLP_SMEM 44032

// =========================================================================
extern "C" void kernel_launch(void* const* d_in, const int* in_sizes, int n_in,
                              void* d_out, int out_size) {
    const float* grid_emb = (const float*)d_in[0];
    const int*   grid     = (const int*)d_in[1];
    const float* sr       = (const float*)d_in[2];
    const float* W1       = (const float*)d_in[3];
    const float* b1       = (const float*)d_in[4];
    const float* W2       = (const float*)d_in[5];
    const float* b2       = (const float*)d_in[6];
    const float* Wp       = (const float*)d_in[7];
    const float* bp       = (const float*)d_in[8];
    const float* gamma    = (const float*)d_in[9];
    const float* beta     = (const float*)d_in[10];
    const float* os       = (const float*)d_in[11];

    cudaFuncSetAttribute(mlp_kernel, cudaFuncAttributeMaxDynamicSharedMemorySize, MLP_SMEM);

    pre_kernel<<<PRE_GRID, 1024>>>(grid_emb, grid, sr, W1, W2, Wp, b2);
    mlp_kernel<<<BB, 256, MLP_SMEM>>>(b1, gamma, beta, bp, os, (float*)d_out);
}

// round 15
// speedup vs baseline: 1.6967x; 1.0048x over previous
#include <cuda_runtime.h>
#include <cuda_bf16.h>
#include <math.h>

#define HH 30
#define WWG 30
#define HW 900
#define DD 256
#define MAXO 16
#define BB 128
#define FPITCH 288   // 261 feature rows padded to 288 (18 K-tiles of 16)
#define CHUNK 1024
#define PF 8

// ---------------- device scratch ----------------
__device__ __align__(16) float g_comb[BB * FPITCH * MAXO];  // [b][feat][k]
__device__ __align__(16) float g_u[BB * DD];
__device__ __align__(16) float g_q[BB * DD];
__device__ float g_bdot[BB];
__device__ __align__(16) float g_r[DD];                     // b2 @ Wp
__device__ int   g_valid[BB * MAXO];
// interleaved fragment-shuffled bf16 weights:
// [(t*8+w)*32+lane] -> 32 bf16 = [qh0(8) | qh1(8) | ql0(8) | ql1(8)]
__device__ __align__(16) __nv_bfloat16 g_W1f[18 * 8 * 32 * 32];
__device__ __align__(16) __nv_bfloat16 g_Ef[16 * 8 * 32 * 32];

__device__ __forceinline__ void bsplit(float x, __nv_bfloat16& h, __nv_bfloat16& l) {
    h = __float2bfloat16(x);
    l = __float2bfloat16(x - __bfloat162float(h));
}
__device__ __forceinline__ unsigned bpack2(__nv_bfloat16 a, __nv_bfloat16 b) {
    return ((unsigned)__bfloat16_as_ushort(b) << 16) | __bfloat16_as_ushort(a);
}
__device__ __forceinline__ void mma16816(float c[4], const unsigned a[4],
                                         unsigned b0, unsigned b1) {
    asm volatile(
        "mma.sync.aligned.m16n8k16.row.col.f32.bf16.bf16.f32 "
        "{%0,%1,%2,%3},{%4,%5,%6,%7},{%8,%9},{%0,%1,%2,%3};"
        : "+f"(c[0]), "+f"(c[1]), "+f"(c[2]), "+f"(c[3])
        : "r"(a[0]), "r"(a[1]), "r"(a[2]), "r"(a[3]), "r"(b0), "r"(b1));
}
__device__ __forceinline__ float gelu(float x) {
    return 0.5f * x * (1.0f + erff(x * 0.70710678118654752f));
}
// weight element (k,n,islo) -> interleaved fragment index (bf16 units)
__device__ __forceinline__ size_t fragidx2(int k, int n, int islo) {
    int t = k >> 4, kk = k & 15;
    int w = n >> 5, nt = (n >> 3) & 3, gq = n & 7;
    int bsel = kk >> 3, tl2 = (kk & 7) >> 1, half = kk & 1;
    int lane = gq * 4 + tl2;
    int sub = islo * 16 + (nt >> 1) * 8 + (nt & 1) * 4 + bsel * 2 + half;
    return (((size_t)(t * 8 + w) * 32 + lane) * 32) + sub;
}

// =========================================================================
// Fused pre-kernel, 1024 threads/block (R13/R14-proven).
// blockIdx: [0,128) ccl, [128,256) prep, [256,288) E, 288 r, [289,307) W1.
// =========================================================================
__global__ __launch_bounds__(1024) void pre_kernel(const float* __restrict__ grid_emb,
                                                   const int* __restrict__ grid,
                                                   const float* __restrict__ sr,
                                                   const float* __restrict__ W1,
                                                   const float* __restrict__ W2,
                                                   const float* __restrict__ Wp,
                                                   const float* __restrict__ b2) {
    int br = blockIdx.x, tid = threadIdx.x;

    __shared__ __align__(16) char spool[46080];
    __shared__ unsigned rootbits[32];
    __shared__ int wpre[32];
    __shared__ int s_flag[2];
    __shared__ int nvalid;
    __shared__ int robj[MAXO], rmin[MAXO], rmax[MAXO], cmin[MAXO], cmax[MAXO];
    __shared__ int offs[MAXO + 1];

    if (br < BB) {
        int* g       = (int*)spool;
        int* lab     = g + HW;
        int* slot_of = lab + HW;
        float* fpool = (float*)(spool + 10816);
        int* ipool   = (int*)(spool + 27200);

        int b = br;
        for (int c = tid; c < HW; c += 1024) {
            int v = grid[b * HW + c];
            g[c] = v;
            lab[c] = (v > 0) ? c : HW;
            slot_of[c] = -1;
        }
        if (tid < 32) rootbits[tid] = 0;
        if (tid == 0) { s_flag[0] = 0; s_flag[1] = 0; }
        __syncthreads();

        for (int it = 0; it < 512; it++) {
            int f = it & 1;
            if (tid == 0) s_flag[1 - f] = 0;
            int changed = 0;
            for (int c = tid; c < HW; c += 1024) {
                int gc = g[c];
                if (gc > 0) {
                    int m = lab[c];
                    int col = c % WWG;
                    if (c >= WWG && g[c - WWG] == gc) { int t = lab[c - WWG]; if (t < m) m = t; }
                    if (c < HW - WWG && g[c + WWG] == gc) { int t = lab[c + WWG]; if (t < m) m = t; }
                    if (col > 0 && g[c - 1] == gc) { int t = lab[c - 1]; if (t < m) m = t; }
                    if (col < WWG - 1 && g[c + 1] == gc) { int t = lab[c + 1]; if (t < m) m = t; }
#pragma unroll
                    for (int hop = 0; hop < 8; hop++) {
                        int p = lab[m];
                        if (p >= m) break;
                        m = p;
                    }
                    if (m < lab[c]) { lab[c] = m; changed = 1; }
                }
            }
            if (changed) s_flag[f] = 1;
            __syncthreads();
            int chg = s_flag[f];
            __syncthreads();
            if (!chg) break;
        }

        for (int c = tid; c < HW; c += 1024)
            if (g[c] > 0 && lab[c] == c) atomicOr(&rootbits[c >> 5], 1u << (c & 31));
        __syncthreads();
        if (tid == 0) {
            int s = 0;
            for (int w = 0; w < 29; w++) { wpre[w] = s; s += __popc(rootbits[w]); }
            nvalid = s < MAXO ? s : MAXO;
        }
        __syncthreads();
        for (int c = tid; c < HW; c += 1024) {
            if (g[c] > 0 && lab[c] == c) {
                int w = c >> 5;
                int rank = wpre[w] + __popc(rootbits[w] & ((1u << (c & 31)) - 1u));
                if (rank < MAXO) { robj[rank] = c; slot_of[c] = rank; }
            }
        }
        if (tid < MAXO) { rmin[tid] = HH; rmax[tid] = -1; cmin[tid] = WWG; cmax[tid] = -1; }
        __syncthreads();
        for (int c = tid; c < HW; c += 1024) {
            if (g[c] > 0) {
                int s = slot_of[lab[c]];
                if (s >= 0) {
                    int r = c / WWG, col = c % WWG;
                    atomicMin(&rmin[s], r); atomicMax(&rmax[s], r);
                    atomicMin(&cmin[s], col); atomicMax(&cmax[s], col);
                }
            }
        }
        __syncthreads();

        int nv = nvalid;
        if (tid == 0) {
            int off = 0;
            for (int k = 0; k < nv; k++) {
                offs[k] = off;
                off += (rmax[k] + 1 - rmin[k]) * (cmax[k] + 1 - cmin[k]);
            }
            offs[nv] = off;
        }
        for (int i = tid; i < MAXO * DD; i += 1024) fpool[i] = 0.f;
        __syncthreads();

        int total = offs[nv];
        int ch = tid & 255, grp = tid >> 8;
        const float* gbase = grid_emb + (size_t)b * HW * DD + ch;
        for (int base = 0; base < total; base += CHUNK) {
            int n = min(CHUNK, total - base);
            for (int e = tid; e < n; e += 1024) {
                int ge = base + e;
                int k = 0;
                while (k + 1 < nv && ge >= offs[k + 1]) k++;
                int local = ge - offs[k];
                int bw = cmax[k] + 1 - cmin[k];
                int li = local / bw, lj = local - li * bw;
                int cell = (rmin[k] + li) * WWG + cmin[k] + lj;
                ipool[e] = (k << 16) | cell;
            }
            __syncthreads();
            int n4 = (n + 3) >> 2;
            int s0 = grp * n4, s1 = min(n, s0 + n4);
            float run = 0.f;
            int prev = -1;
            for (int e0b = s0; e0b < s1; e0b += PF) {
                int m = s1 - e0b; if (m > PF) m = PF;
                float v[PF]; int kk[PF];
#pragma unroll
                for (int j = 0; j < PF; j++) {
                    if (j < m) {
                        int ent = ipool[e0b + j];
                        kk[j] = ent >> 16;
                        v[j] = gbase[(size_t)(ent & 0xffff) * DD];
                    }
                }
#pragma unroll
                for (int j = 0; j < PF; j++) {
                    if (j < m) {
                        if (kk[j] != prev) {
                            if (prev >= 0) atomicAdd(&fpool[prev * DD + ch], run);
                            run = 0.f;
                            prev = kk[j];
                        }
                        run += v[j];
                    }
                }
            }
            if (prev >= 0) atomicAdd(&fpool[prev * DD + ch], run);
            __syncthreads();
        }

        float* cb = g_comb + (size_t)b * FPITCH * MAXO;
        for (int i = tid; i < FPITCH * MAXO; i += 1024) cb[i] = 0.f;
        if (tid < MAXO) g_valid[b * MAXO + tid] = (tid < nv) ? 1 : 0;
        __syncthreads();
        if (tid < DD) {
            for (int k = 0; k < nv; k++) {
                int y = rmin[k], x = cmin[k];
                int h = rmax[k] + 1 - y, w = cmax[k] + 1 - x;
                cb[tid * MAXO + k] = fpool[k * DD + tid] / (float)(h * w);
                if (tid < 5) {
                    float v;
                    int color = g[robj[k]];
                    if (tid == 0)      v = (float)color * (1.0f / 9.0f);
                    else if (tid == 1) v = (float)x * (1.0f / WWG);
                    else if (tid == 2) v = (float)y * (1.0f / HH);
                    else if (tid == 3) v = (float)w * (1.0f / WWG);
                    else               v = (float)h * (1.0f / HH);
                    cb[(DD + tid) * MAXO + k] = v;
                }
            }
        }
    } else if (br < 2 * BB) {
        // ---------------- prep: sn, u, q, bdot ----------------
        int b = br - BB;
        float* sn   = (float*)spool;
        float* sred = sn + DD;
        float s = 0.f;
        if (tid < DD) {
            const float* base = sr + (size_t)b * 8 * DD + tid;
#pragma unroll
            for (int j = 0; j < 8; j++) s += base[j * DD];
            s *= 0.125f;
            sred[tid] = s * s;
        }
        __syncthreads();
        for (int off = 128; off; off >>= 1) {
            if (tid < off) sred[tid] += sred[tid + off];
            __syncthreads();
        }
        float nrm = sqrtf(sred[0]);
        __syncthreads();
        float snv = s / fmaxf(nrm, 1e-8f);
        if (tid < DD) { sn[tid] = snv; sred[tid] = snv * b2[tid]; }
        __syncthreads();
        for (int off = 128; off; off >>= 1) {
            if (tid < off) sred[tid] += sred[tid + off];
            __syncthreads();
        }
        if (tid == 0) g_bdot[b] = sred[0];

        if (tid < DD) {
            float acc = 0.f;
#pragma unroll 8
            for (int d = 0; d < DD; d++) acc += sn[d] * Wp[d * DD + tid];
            g_q[b * DD + tid] = acc;
        }

        int wid = tid >> 5, lane = tid & 31;
        for (int d = wid; d < DD; d += 32) {
            float a = 0.f;
            const float* wr = W2 + d * DD;
#pragma unroll 4
            for (int e2 = lane; e2 < DD; e2 += 32) a += wr[e2] * sn[e2];
#pragma unroll
            for (int off = 16; off; off >>= 1) a += __shfl_down_sync(0xffffffffu, a, off);
            if (lane == 0) g_u[b * DD + d] = a;
        }
    } else if (br < 2 * BB + 32) {
        // ---- E rows -> interleaved fragment bf16 (E[k=d][n=e]) ----
        int d0 = (br - 2 * BB) * 8;
        int e = tid & 255, sub = tid >> 8;
        int r0 = sub * 2;
        float* wpt = (float*)spool;
        float* w2s = (float*)(spool + 32768);
        for (int i = tid; i < 8 * DD; i += 1024) w2s[i] = W2[d0 * DD + i];
        const float4* wp4 = (const float4*)Wp;
        float4 pf0 = wp4[tid], pf1 = wp4[tid + 1024];
        __syncthreads();
        float a0 = 0.f, a1 = 0.f;
        for (int t = 0; t < 8; t++) {
            ((float4*)wpt)[tid] = pf0;
            ((float4*)wpt)[tid + 1024] = pf1;
            __syncthreads();
            if (t < 7) {
                pf0 = wp4[(t + 1) * 2048 + tid];
                pf1 = wp4[(t + 1) * 2048 + tid + 1024];
            }
#pragma unroll 8
            for (int k = 0; k < 32; k++) {
                float wp = wpt[k * 256 + e];
                a0 += w2s[r0 * DD + t * 32 + k] * wp;
                a1 += w2s[(r0 + 1) * DD + t * 32 + k] * wp;
            }
            __syncthreads();
        }
        __nv_bfloat16 h, l;
        bsplit(a0, h, l);
        g_Ef[fragidx2(d0 + r0, e, 0)] = h;
        g_Ef[fragidx2(d0 + r0, e, 1)] = l;
        bsplit(a1, h, l);
        g_Ef[fragidx2(d0 + r0 + 1, e, 0)] = h;
        g_Ef[fragidx2(d0 + r0 + 1, e, 1)] = l;
    } else if (br == 2 * BB + 32) {
        if (tid < DD) {
            float a = 0.f;
#pragma unroll 8
            for (int k = 0; k < DD; k++) a += b2[k] * Wp[k * DD + tid];
            g_r[tid] = a;
        }
    } else {
        // ---- W1 (261x256, pad to 288) -> interleaved fragment bf16 ----
        int i = (br - (2 * BB + 33)) * 1024 + tid;   // float4 idx 0..18431
        if (i < (FPITCH * DD) / 4) {
            const float4* w14 = (const float4*)W1;   // 16704 real float4s
            float4 v = make_float4(0.f, 0.f, 0.f, 0.f);
            if (i < 16704) v = w14[i];
            int k = i >> 6;
            int n0 = (i & 63) * 4;
            float vals[4] = {v.x, v.y, v.z, v.w};
#pragma unroll
            for (int c = 0; c < 4; c++) {
                __nv_bfloat16 h, l;
                bsplit(vals[c], h, l);
                g_W1f[fragidx2(k, n0 + c, 0)] = h;
                g_W1f[fragidx2(k, n0 + c, 1)] = l;
            }
        }
    }
}
#define PRE_GRID (2 * BB + 33 + 18)   // 307

// per-thread 64B weight block load (4 x LDG.128 at immediate offsets)
#define LOADW(dst, arr, t, warp, lane)                                      \
    {                                                                       \
        const uint4* _p = (arr) + (((size_t)(t) * 8 + (warp)) * 32 + (lane)) * 4; \
        (dst)[0] = _p[0]; (dst)[1] = _p[1]; (dst)[2] = _p[2]; (dst)[3] = _p[3];   \
    }

// =========================================================================
// Tensor-core MLP v4: interleaved fragment-streamed weights, depth-4
// software pipeline, no barriers in GEMM loops. One block = one batch.
// =========================================================================
__global__ __launch_bounds__(256) void mlp_kernel(const float* __restrict__ b1v,
                                                  const float* __restrict__ gv,
                                                  const float* __restrict__ btv,
                                                  const float* __restrict__ bpv,
                                                  const float* __restrict__ osp,
                                                  float* __restrict__ out) {
    int b = blockIdx.x, tid = threadIdx.x;
    int warp = tid >> 5, lane = tid & 31;
    int g = lane >> 2, tl = lane & 3;

    extern __shared__ char smraw[];
    __nv_bfloat16* A1h = (__nv_bfloat16*)(smraw);            // 16 x 296
    __nv_bfloat16* A1l = (__nv_bfloat16*)(smraw + 9472);
    __nv_bfloat16* A2h = (__nv_bfloat16*)(smraw + 18944);    // 16 x 264
    __nv_bfloat16* A2l = (__nv_bfloat16*)(smraw + 27392);
    float* u_s  = (float*)(smraw + 35840);
    float* q_s  = (float*)(smraw + 36864);
    float* r_s  = (float*)(smraw + 37888);
    float* bp_s = (float*)(smraw + 38912);
    float* gm_s = (float*)(smraw + 39936);
    float* bt_s = (float*)(smraw + 40960);
    float* b1_s = (float*)(smraw + 41984);
    float* redA = (float*)(smraw + 43008);   // [16][8]
    float* redB = (float*)(smraw + 43520);   // [16][8]
    __shared__ float dots[MAXO], mur[MAXO], rstd[MAXO], s_bd[2];
    __shared__ int vld[MAXO];

    const uint4* wf = (const uint4*)g_W1f;
    const uint4* ef = (const uint4*)g_Ef;

    // pipeline prologue for GEMM1 (issue before A1 staging to hide latency)
    uint4 buf[4][4];
    LOADW(buf[0], wf, 0, warp, lane);
    LOADW(buf[1], wf, 1, warp, lane);
    LOADW(buf[2], wf, 2, warp, lane);
    LOADW(buf[3], wf, 3, warp, lane);

    // ---- stage A1 + constants ----
    const float* cbase = g_comb + (size_t)b * FPITCH * MAXO;
    for (int i = tid; i < FPITCH * MAXO; i += 256) {
        float x = cbase[i];
        int feat = i >> 4, obj = i & 15;
        __nv_bfloat16 h, l;
        bsplit(x, h, l);
        A1h[obj * 296 + feat] = h;
        A1l[obj * 296 + feat] = l;
    }
    u_s[tid] = g_u[b * DD + tid];
    q_s[tid] = g_q[b * DD + tid];
    r_s[tid] = g_r[tid];
    bp_s[tid] = bpv[tid];
    gm_s[tid] = gv[tid];
    bt_s[tid] = btv[tid];
    b1_s[tid] = b1v[tid];
    if (tid < MAXO) vld[tid] = g_valid[b * MAXO + tid];
    if (tid == 0) { s_bd[0] = g_bdot[b]; s_bd[1] = osp[0]; }
    __syncthreads();

    // ============ GEMM1: hidden = gelu(A1 @ W1 + b1), 18 tiles ============
    float c1[4][4];
#pragma unroll
    for (int nt = 0; nt < 4; nt++)
#pragma unroll
        for (int j = 0; j < 4; j++) c1[nt][j] = 0.f;

#pragma unroll
    for (int t = 0; t < 18; t++) {
        uint4 q0 = buf[t & 3][0], q1 = buf[t & 3][1];
        uint4 q2 = buf[t & 3][2], q3 = buf[t & 3][3];
        if (t + 4 < 18) LOADW(buf[t & 3], wf, t + 4, warp, lane);

        unsigned ah[4], al[4];
        int k0 = 16 * t + 2 * tl;
        ah[0] = *(const unsigned*)(A1h + g * 296 + k0);
        ah[1] = *(const unsigned*)(A1h + (g + 8) * 296 + k0);
        ah[2] = *(const unsigned*)(A1h + g * 296 + k0 + 8);
        ah[3] = *(const unsigned*)(A1h + (g + 8) * 296 + k0 + 8);
        al[0] = *(const unsigned*)(A1l + g * 296 + k0);
        al[1] = *(const unsigned*)(A1l + (g + 8) * 296 + k0);
        al[2] = *(const unsigned*)(A1l + g * 296 + k0 + 8);
        al[3] = *(const unsigned*)(A1l + (g + 8) * 296 + k0 + 8);

        mma16816(c1[0], ah, q0.x, q0.y);
        mma16816(c1[0], al, q0.x, q0.y);
        mma16816(c1[0], ah, q2.x, q2.y);
        mma16816(c1[1], ah, q0.z, q0.w);
        mma16816(c1[1], al, q0.z, q0.w);
        mma16816(c1[1], ah, q2.z, q2.w);
        mma16816(c1[2], ah, q1.x, q1.y);
        mma16816(c1[2], al, q1.x, q1.y);
        mma16816(c1[2], ah, q3.x, q3.y);
        mma16816(c1[3], ah, q1.z, q1.w);
        mma16816(c1[3], al, q1.z, q1.w);
        mma16816(c1[3], ah, q3.z, q3.w);
    }

    // GEMM2 pipeline prologue (hidden by gelu/dot epilogue below)
    LOADW(buf[0], ef, 0, warp, lane);
    LOADW(buf[1], ef, 1, warp, lane);
    LOADW(buf[2], ef, 2, warp, lane);
    LOADW(buf[3], ef, 3, warp, lane);

    // ---- gelu + hidden->A2 + dot partials ----
    float bdot = s_bd[0], os = s_bd[1];
    float dpA = 0.f, dpB = 0.f;
#pragma unroll
    for (int nt = 0; nt < 4; nt++) {
        int col = (warp * 4 + nt) * 8 + 2 * tl;
        float h0 = gelu(c1[nt][0] + b1_s[col]);
        float h1 = gelu(c1[nt][1] + b1_s[col + 1]);
        float h2 = gelu(c1[nt][2] + b1_s[col]);
        float h3 = gelu(c1[nt][3] + b1_s[col + 1]);
        dpA += h0 * u_s[col] + h1 * u_s[col + 1];
        dpB += h2 * u_s[col] + h3 * u_s[col + 1];
        __nv_bfloat16 e0, f0, e1, f1;
        bsplit(h0, e0, f0); bsplit(h1, e1, f1);
        *(unsigned*)(A2h + g * 264 + col) = bpack2(e0, e1);
        *(unsigned*)(A2l + g * 264 + col) = bpack2(f0, f1);
        bsplit(h2, e0, f0); bsplit(h3, e1, f1);
        *(unsigned*)(A2h + (g + 8) * 264 + col) = bpack2(e0, e1);
        *(unsigned*)(A2l + (g + 8) * 264 + col) = bpack2(f0, f1);
    }
    dpA += __shfl_xor_sync(0xffffffffu, dpA, 1);
    dpA += __shfl_xor_sync(0xffffffffu, dpA, 2);
    dpB += __shfl_xor_sync(0xffffffffu, dpB, 1);
    dpB += __shfl_xor_sync(0xffffffffu, dpB, 2);
    if (tl == 0) {
        redA[g * 8 + warp] = dpA;
        redA[(g + 8) * 8 + warp] = dpB;
    }
    __syncthreads();
    if (tid < MAXO) {
        float s = 0.f;
#pragma unroll
        for (int w = 0; w < 8; w++) s += redA[tid * 8 + w];
        dots[tid] = s + bdot;
    }

    // ============ GEMM2: hE = hidden @ E, 16 tiles ============
    float c2[4][4];
#pragma unroll
    for (int nt = 0; nt < 4; nt++)
#pragma unroll
        for (int j = 0; j < 4; j++) c2[nt][j] = 0.f;

#pragma unroll
    for (int t = 0; t < 16; t++) {
        uint4 q0 = buf[t & 3][0], q1 = buf[t & 3][1];
        uint4 q2 = buf[t & 3][2], q3 = buf[t & 3][3];
        if (t + 4 < 16) LOADW(buf[t & 3], ef, t + 4, warp, lane);

        unsigned ah[4], al[4];
        int k0 = 16 * t + 2 * tl;
        ah[0] = *(const unsigned*)(A2h + g * 264 + k0);
        ah[1] = *(const unsigned*)(A2h + (g + 8) * 264 + k0);
        ah[2] = *(const unsigned*)(A2h + g * 264 + k0 + 8);
        ah[3] = *(const unsigned*)(A2h + (g + 8) * 264 + k0 + 8);
        al[0] = *(const unsigned*)(A2l + g * 264 + k0);
        al[1] = *(const unsigned*)(A2l + (g + 8) * 264 + k0);
        al[2] = *(const unsigned*)(A2l + g * 264 + k0 + 8);
        al[3] = *(const unsigned*)(A2l + (g + 8) * 264 + k0 + 8);

        mma16816(c2[0], ah, q0.x, q0.y);
        mma16816(c2[0], al, q0.x, q0.y);
        mma16816(c2[0], ah, q2.x, q2.y);
        mma16816(c2[1], ah, q0.z, q0.w);
        mma16816(c2[1], al, q0.z, q0.w);
        mma16816(c2[1], ah, q2.z, q2.w);
        mma16816(c2[2], ah, q1.x, q1.y);
        mma16816(c2[2], al, q1.x, q1.y);
        mma16816(c2[2], ah, q3.x, q3.y);
        mma16816(c2[3], ah, q1.z, q1.w);
        mma16816(c2[3], al, q1.z, q1.w);
        mma16816(c2[3], ah, q3.z, q3.w);
    }
    __syncthreads();   // dots visible; A2 reads done

    // ---- epilogue: pre = os*(hE + r - dot*q) + bp ; invalid -> bp ----
    float prer[4][4];
    float dA = dots[g], dB = dots[g + 8];
    int vA = vld[g], vB = vld[g + 8];
#pragma unroll
    for (int nt = 0; nt < 4; nt++) {
        int col = (warp * 4 + nt) * 8 + 2 * tl;
        float r0v = r_s[col], r1v = r_s[col + 1];
        float q0 = q_s[col], q1 = q_s[col + 1];
        float bp0 = bp_s[col], bp1 = bp_s[col + 1];
        float p0 = os * (c2[nt][0] + r0v - dA * q0) + bp0;
        float p1 = os * (c2[nt][1] + r1v - dA * q1) + bp1;
        float p2 = os * (c2[nt][2] + r0v - dB * q0) + bp0;
        float p3 = os * (c2[nt][3] + r1v - dB * q1) + bp1;
        prer[nt][0] = vA ? p0 : bp0;
        prer[nt][1] = vA ? p1 : bp1;
        prer[nt][2] = vB ? p2 : bp0;
        prer[nt][3] = vB ? p3 : bp1;
    }

    // ---- layernorm ----
    float psA = 0.f, pqA = 0.f, psB = 0.f, pqB = 0.f;
#pragma unroll
    for (int nt = 0; nt < 4; nt++) {
        psA += prer[nt][0] + prer[nt][1];
        pqA += prer[nt][0] * prer[nt][0] + prer[nt][1] * prer[nt][1];
        psB += prer[nt][2] + prer[nt][3];
        pqB += prer[nt][2] * prer[nt][2] + prer[nt][3] * prer[nt][3];
    }
    psA += __shfl_xor_sync(0xffffffffu, psA, 1);
    psA += __shfl_xor_sync(0xffffffffu, psA, 2);
    pqA += __shfl_xor_sync(0xffffffffu, pqA, 1);
    pqA += __shfl_xor_sync(0xffffffffu, pqA, 2);
    psB += __shfl_xor_sync(0xffffffffu, psB, 1);
    psB += __shfl_xor_sync(0xffffffffu, psB, 2);
    pqB += __shfl_xor_sync(0xffffffffu, pqB, 1);
    pqB += __shfl_xor_sync(0xffffffffu, pqB, 2);
    if (tl == 0) {
        redA[g * 8 + warp] = psA;
        redA[(g + 8) * 8 + warp] = psB;
        redB[g * 8 + warp] = pqA;
        redB[(g + 8) * 8 + warp] = pqB;
    }
    __syncthreads();
    if (tid < MAXO) {
        float s = 0.f, sq = 0.f;
#pragma unroll
        for (int w = 0; w < 8; w++) { s += redA[tid * 8 + w]; sq += redB[tid * 8 + w]; }
        float m = s * (1.0f / DD);
        mur[tid] = m;
        float va = sq * (1.0f / DD) - m * m;
        rstd[tid] = rsqrtf(va + 1e-5f);
    }
    __syncthreads();

    float mA = mur[g], rsA = rstd[g], mB = mur[g + 8], rsB = rstd[g + 8];
#pragma unroll
    for (int nt = 0; nt < 4; nt++) {
        int col = (warp * 4 + nt) * 8 + 2 * tl;
        float g0 = gm_s[col], g1 = gm_s[col + 1];
        float t0 = bt_s[col], t1 = bt_s[col + 1];
        float2 o0, o1;
        o0.x = (prer[nt][0] - mA) * rsA * g0 + t0;
        o0.y = (prer[nt][1] - mA) * rsA * g1 + t1;
        o1.x = (prer[nt][2] - mB) * rsB * g0 + t0;
        o1.y = (prer[nt][3] - mB) * rsB * g1 + t1;
        *(float2*)&out[((size_t)(b * MAXO + g)) * DD + col] = o0;
        *(float2*)&out[((size_t)(b * MAXO + g + 8)) * DD + col] = o1;
    }
}

#define MLP_SMEM 44032

// =========================================================================
extern "C" void kernel_launch(void* const* d_in, const int* in_sizes, int n_in,
                              void* d_out, int out_size) {
    const float* grid_emb = (const float*)d_in[0];
    const int*   grid     = (const int*)d_in[1];
    const float* sr       = (const float*)d_in[2];
    const float* W1       = (const float*)d_in[3];
    const float* b1       = (const float*)d_in[4];
    const float* W2       = (const float*)d_in[5];
    const float* b2       = (const float*)d_in[6];
    const float* Wp       = (const float*)d_in[7];
    const float* bp       = (const float*)d_in[8];
    const float* gamma    = (const float*)d_in[9];
    const float* beta     = (const float*)d_in[10];
    const float* os       = (const float*)d_in[11];

    cudaFuncSetAttribute(mlp_kernel, cudaFuncAttributeMaxDynamicSharedMemorySize, MLP_SMEM);

    pre_kernel<<<PRE_GRID, 1024>>>(grid_emb, grid, sr, W1, W2, Wp, b2);
    mlp_kernel<<<BB, 256, MLP_SMEM>>>(b1, gamma, beta, bp, os, (float*)d_out);
}

// round 16
// speedup vs baseline: 1.7363x; 1.0234x over previous
#include <cuda_runtime.h>
#include <cuda_bf16.h>
#include <math.h>

#define HH 30
#define WWG 30
#define HW 900
#define DD 256
#define MAXO 16
#define BB 128
#define FPITCH 288   // 261 feature rows padded to 288 (18 K-tiles of 16)
#define CHUNK 1024
#define PF 16

#define BAR(id, cnt) asm volatile("bar.sync %0, %1;" :: "r"(id), "r"(cnt) : "memory")

// ---------------- device scratch ----------------
__device__ __align__(16) float g_comb[BB * FPITCH * MAXO];  // [b][feat][k]
__device__ __align__(16) float g_u[BB * DD];
__device__ __align__(16) float g_q[BB * DD];
__device__ float g_bdot[BB];
__device__ __align__(16) float g_r[DD];                     // b2 @ Wp
__device__ int   g_valid[BB * MAXO];
// interleaved fragment-shuffled bf16 weights:
// [(t*8+w)*32+lane] -> 32 bf16 = [qh0(8) | qh1(8) | ql0(8) | ql1(8)]
__device__ __align__(16) __nv_bfloat16 g_W1f[18 * 8 * 32 * 32];
__device__ __align__(16) __nv_bfloat16 g_Ef[16 * 8 * 32 * 32];

__device__ __forceinline__ void bsplit(float x, __nv_bfloat16& h, __nv_bfloat16& l) {
    h = __float2bfloat16(x);
    l = __float2bfloat16(x - __bfloat162float(h));
}
__device__ __forceinline__ unsigned bpack2(__nv_bfloat16 a, __nv_bfloat16 b) {
    return ((unsigned)__bfloat16_as_ushort(b) << 16) | __bfloat16_as_ushort(a);
}
__device__ __forceinline__ void mma16816(float c[4], const unsigned a[4],
                                         unsigned b0, unsigned b1) {
    asm volatile(
        "mma.sync.aligned.m16n8k16.row.col.f32.bf16.bf16.f32 "
        "{%0,%1,%2,%3},{%4,%5,%6,%7},{%8,%9},{%0,%1,%2,%3};"
        : "+f"(c[0]), "+f"(c[1]), "+f"(c[2]), "+f"(c[3])
        : "r"(a[0]), "r"(a[1]), "r"(a[2]), "r"(a[3]), "r"(b0), "r"(b1));
}
__device__ __forceinline__ float gelu(float x) {
    return 0.5f * x * (1.0f + erff(x * 0.70710678118654752f));
}
// weight element (k,n,islo) -> interleaved fragment index (bf16 units)
__device__ __forceinline__ size_t fragidx2(int k, int n, int islo) {
    int t = k >> 4, kk = k & 15;
    int w = n >> 5, nt = (n >> 3) & 3, gq = n & 7;
    int bsel = kk >> 3, tl2 = (kk & 7) >> 1, half = kk & 1;
    int lane = gq * 4 + tl2;
    int sub = islo * 16 + (nt >> 1) * 8 + (nt & 1) * 4 + bsel * 2 + half;
    return (((size_t)(t * 8 + w) * 32 + lane) * 32) + sub;
}

// =========================================================================
// Single-wave warp-specialized pre-kernel. 128 blocks x 1024 threads.
// warps 0-7: CCL+features (bar 1); warps 8-15: prep (bar 2);
// warps 16-31: W1-pad slice + 2 E rows (+ r on block 127) (bar 3).
// =========================================================================
__global__ __launch_bounds__(1024) void pre_kernel(const float* __restrict__ grid_emb,
                                                   const int* __restrict__ grid,
                                                   const float* __restrict__ sr,
                                                   const float* __restrict__ W1,
                                                   const float* __restrict__ W2,
                                                   const float* __restrict__ Wp,
                                                   const float* __restrict__ b2) {
    int b = blockIdx.x, tid = threadIdx.x;

    __shared__ __align__(16) char spool[35392];
    __shared__ unsigned rootbits[32];
    __shared__ int wpre[32];
    __shared__ int s_flag[2];
    __shared__ int nvalid;
    __shared__ int robj[MAXO], rmin[MAXO], rmax[MAXO], cmin[MAXO], cmax[MAXO];
    __shared__ int offs[MAXO + 1];

    int* g       = (int*)spool;                    // 3600
    int* lab     = g + HW;                         // 3600
    int* slot_of = lab + HW;                       // 3600 -> 10800
    float* fpool = (float*)(spool + 10816);        // 16384 -> 27200
    int* ipool   = (int*)(spool + 27200);          // 4096  -> 31296
    float* sn    = (float*)(spool + 31296);        // 1024
    float* sred  = (float*)(spool + 32320);        // 1024
    float* w2s2  = (float*)(spool + 33344);        // 2048

    if (tid < 256) {
        // ================= GROUP A: CCL + features (proven R8 branch) =========
        for (int c = tid; c < HW; c += 256) {
            int v = grid[b * HW + c];
            g[c] = v;
            lab[c] = (v > 0) ? c : HW;
            slot_of[c] = -1;
        }
        if (tid < 32) rootbits[tid] = 0;
        if (tid == 0) { s_flag[0] = 0; s_flag[1] = 0; }
        BAR(1, 256);

        for (int it = 0; it < 512; it++) {
            int f = it & 1;
            if (tid == 0) s_flag[1 - f] = 0;
            int changed = 0;
            for (int c = tid; c < HW; c += 256) {
                int gc = g[c];
                if (gc > 0) {
                    int m = lab[c];
                    int col = c % WWG;
                    if (c >= WWG && g[c - WWG] == gc) { int t = lab[c - WWG]; if (t < m) m = t; }
                    if (c < HW - WWG && g[c + WWG] == gc) { int t = lab[c + WWG]; if (t < m) m = t; }
                    if (col > 0 && g[c - 1] == gc) { int t = lab[c - 1]; if (t < m) m = t; }
                    if (col < WWG - 1 && g[c + 1] == gc) { int t = lab[c + 1]; if (t < m) m = t; }
#pragma unroll
                    for (int hop = 0; hop < 8; hop++) {
                        int p = lab[m];
                        if (p >= m) break;
                        m = p;
                    }
                    if (m < lab[c]) { lab[c] = m; changed = 1; }
                }
            }
            if (changed) s_flag[f] = 1;
            BAR(1, 256);
            int chg = s_flag[f];
            BAR(1, 256);
            if (!chg) break;
        }

        for (int c = tid; c < HW; c += 256)
            if (g[c] > 0 && lab[c] == c) atomicOr(&rootbits[c >> 5], 1u << (c & 31));
        BAR(1, 256);
        if (tid == 0) {
            int s = 0;
            for (int w = 0; w < 29; w++) { wpre[w] = s; s += __popc(rootbits[w]); }
            nvalid = s < MAXO ? s : MAXO;
        }
        BAR(1, 256);
        for (int c = tid; c < HW; c += 256) {
            if (g[c] > 0 && lab[c] == c) {
                int w = c >> 5;
                int rank = wpre[w] + __popc(rootbits[w] & ((1u << (c & 31)) - 1u));
                if (rank < MAXO) { robj[rank] = c; slot_of[c] = rank; }
            }
        }
        if (tid < MAXO) { rmin[tid] = HH; rmax[tid] = -1; cmin[tid] = WWG; cmax[tid] = -1; }
        BAR(1, 256);
        for (int c = tid; c < HW; c += 256) {
            if (g[c] > 0) {
                int s = slot_of[lab[c]];
                if (s >= 0) {
                    int r = c / WWG, col = c % WWG;
                    atomicMin(&rmin[s], r); atomicMax(&rmax[s], r);
                    atomicMin(&cmin[s], col); atomicMax(&cmax[s], col);
                }
            }
        }
        BAR(1, 256);

        int nv = nvalid;
        if (tid == 0) {
            int off = 0;
            for (int k = 0; k < nv; k++) {
                offs[k] = off;
                off += (rmax[k] + 1 - rmin[k]) * (cmax[k] + 1 - cmin[k]);
            }
            offs[nv] = off;
        }
        for (int i = tid; i < MAXO * DD; i += 256) fpool[i] = 0.f;
        BAR(1, 256);

        int total = offs[nv];
        float run = 0.f;
        int prev = -1;
        const float* gbase = grid_emb + (size_t)b * HW * DD + tid;
        for (int base = 0; base < total; base += CHUNK) {
            int n = min(CHUNK, total - base);
            for (int e = tid; e < n; e += 256) {
                int ge = base + e;
                int k = 0;
                while (k + 1 < nv && ge >= offs[k + 1]) k++;
                int local = ge - offs[k];
                int bw = cmax[k] + 1 - cmin[k];
                int li = local / bw, lj = local - li * bw;
                int cell = (rmin[k] + li) * WWG + cmin[k] + lj;
                ipool[e] = (k << 16) | cell;
            }
            BAR(1, 256);
            for (int e0b = 0; e0b < n; e0b += PF) {
                int m = n - e0b; if (m > PF) m = PF;
                float v[PF]; int kk[PF];
#pragma unroll
                for (int j = 0; j < PF; j++) {
                    if (j < m) {
                        int ent = ipool[e0b + j];
                        kk[j] = ent >> 16;
                        v[j] = gbase[(size_t)(ent & 0xffff) * DD];
                    }
                }
#pragma unroll
                for (int j = 0; j < PF; j++) {
                    if (j < m) {
                        if (kk[j] != prev) {
                            if (prev >= 0) fpool[prev * DD + tid] += run;
                            run = 0.f;
                            prev = kk[j];
                        }
                        run += v[j];
                    }
                }
            }
            BAR(1, 256);
        }
        if (prev >= 0) fpool[prev * DD + tid] += run;
        BAR(1, 256);

        float* cb = g_comb + (size_t)b * FPITCH * MAXO;
        for (int i = tid; i < FPITCH * MAXO; i += 256) cb[i] = 0.f;
        if (tid < MAXO) g_valid[b * MAXO + tid] = (tid < nv) ? 1 : 0;
        BAR(1, 256);
        for (int k = 0; k < nv; k++) {
            int y = rmin[k], x = cmin[k];
            int h = rmax[k] + 1 - y, w = cmax[k] + 1 - x;
            cb[tid * MAXO + k] = fpool[k * DD + tid] / (float)(h * w);
            if (tid < 5) {
                float v;
                int color = g[robj[k]];
                if (tid == 0)      v = (float)color * (1.0f / 9.0f);
                else if (tid == 1) v = (float)x * (1.0f / WWG);
                else if (tid == 2) v = (float)y * (1.0f / HH);
                else if (tid == 3) v = (float)w * (1.0f / WWG);
                else               v = (float)h * (1.0f / HH);
                cb[(DD + tid) * MAXO + k] = v;
            }
        }
    } else if (tid < 512) {
        // ================= GROUP B: prep (proven R8 branch) =================
        int t2 = tid - 256;
        float s = 0.f;
        const float* base = sr + (size_t)b * 8 * DD + t2;
#pragma unroll
        for (int j = 0; j < 8; j++) s += base[j * DD];
        s *= 0.125f;
        sred[t2] = s * s; BAR(2, 256);
        for (int off = 128; off; off >>= 1) {
            if (t2 < off) sred[t2] += sred[t2 + off];
            BAR(2, 256);
        }
        float nrm = sqrtf(sred[0]);
        BAR(2, 256);
        float snv = s / fmaxf(nrm, 1e-8f);
        sn[t2] = snv;
        sred[t2] = snv * b2[t2]; BAR(2, 256);
        for (int off = 128; off; off >>= 1) {
            if (t2 < off) sred[t2] += sred[t2 + off];
            BAR(2, 256);
        }
        if (t2 == 0) g_bdot[b] = sred[0];

        float acc = 0.f;
#pragma unroll 8
        for (int d = 0; d < DD; d++) acc += sn[d] * Wp[d * DD + t2];
        g_q[b * DD + t2] = acc;

        int wid = t2 >> 5, lane = t2 & 31;
        for (int d = wid; d < DD; d += 8) {
            float a = 0.f;
            const float* wr = W2 + d * DD;
#pragma unroll 4
            for (int e2 = lane; e2 < DD; e2 += 32) a += wr[e2] * sn[e2];
#pragma unroll
            for (int off = 16; off; off >>= 1) a += __shfl_down_sync(0xffffffffu, a, off);
            if (lane == 0) g_u[b * DD + d] = a;
        }
    } else {
        // ============ GROUP C: W1-pad slice + 2 E rows (+ r) ============
        int t3 = tid - 512;
        // W1 pad: 144 float4 per block
        if (t3 < 144) {
            int i = b * 144 + t3;
            const float4* w14 = (const float4*)W1;   // 16704 real float4s
            float4 v = make_float4(0.f, 0.f, 0.f, 0.f);
            if (i < 16704) v = w14[i];
            int k = i >> 6;
            int n0 = (i & 63) * 4;
            float vals[4] = {v.x, v.y, v.z, v.w};
#pragma unroll
            for (int c = 0; c < 4; c++) {
                __nv_bfloat16 h, l;
                bsplit(vals[c], h, l);
                g_W1f[fragidx2(k, n0 + c, 0)] = h;
                g_W1f[fragidx2(k, n0 + c, 1)] = l;
            }
        }
        // E rows 2b, 2b+1: stage W2 rows, then 512 threads = 2 rows x 256 cols
        int d0 = 2 * b;
        for (int i = t3; i < 2 * DD; i += 512) w2s2[i] = W2[d0 * DD + i];
        BAR(3, 512);
        int e = t3 & 255, sub = t3 >> 8;
        const float* w2row = w2s2 + sub * DD;
        float acc = 0.f;
#pragma unroll 8
        for (int k = 0; k < DD; k++) acc += w2row[k] * Wp[k * DD + e];
        __nv_bfloat16 h, l;
        bsplit(acc, h, l);
        g_Ef[fragidx2(d0 + sub, e, 0)] = h;
        g_Ef[fragidx2(d0 + sub, e, 1)] = l;
        // r = b2 @ Wp on block 127
        if (b == BB - 1 && t3 < DD) {
            float a = 0.f;
#pragma unroll 8
            for (int k = 0; k < DD; k++) a += b2[k] * Wp[k * DD + t3];
            g_r[t3] = a;
        }
    }
}
#define PRE_GRID BB   // 128 blocks, one wave

// per-thread 64B weight block load (4 x LDG.128 at immediate offsets)
#define LOADW(dst, arr, t, warp, lane)                                      \
    {                                                                       \
        const uint4* _p = (arr) + (((size_t)(t) * 8 + (warp)) * 32 + (lane)) * 4; \
        (dst)[0] = _p[0]; (dst)[1] = _p[1]; (dst)[2] = _p[2]; (dst)[3] = _p[3];   \
    }

// =========================================================================
// Tensor-core MLP (R15-proven): interleaved fragment-streamed weights,
// depth-4 software pipeline, no barriers in GEMM loops.
// =========================================================================
__global__ __launch_bounds__(256) void mlp_kernel(const float* __restrict__ b1v,
                                                  const float* __restrict__ gv,
                                                  const float* __restrict__ btv,
                                                  const float* __restrict__ bpv,
                                                  const float* __restrict__ osp,
                                                  float* __restrict__ out) {
    int b = blockIdx.x, tid = threadIdx.x;
    int warp = tid >> 5, lane = tid & 31;
    int g = lane >> 2, tl = lane & 3;

    extern __shared__ char smraw[];
    __nv_bfloat16* A1h = (__nv_bfloat16*)(smraw);            // 16 x 296
    __nv_bfloat16* A1l = (__nv_bfloat16*)(smraw + 9472);
    __nv_bfloat16* A2h = (__nv_bfloat16*)(smraw + 18944);    // 16 x 264
    __nv_bfloat16* A2l = (__nv_bfloat16*)(smraw + 27392);
    float* u_s  = (float*)(smraw + 35840);
    float* q_s  = (float*)(smraw + 36864);
    float* r_s  = (float*)(smraw + 37888);
    float* bp_s = (float*)(smraw + 38912);
    float* gm_s = (float*)(smraw + 39936);
    float* bt_s = (float*)(smraw + 40960);
    float* b1_s = (float*)(smraw + 41984);
    float* redA = (float*)(smraw + 43008);   // [16][8]
    float* redB = (float*)(smraw + 43520);   // [16][8]
    __shared__ float dots[MAXO], mur[MAXO], rstd[MAXO], s_bd[2];
    __shared__ int vld[MAXO];

    const uint4* wf = (const uint4*)g_W1f;
    const uint4* ef = (const uint4*)g_Ef;

    uint4 buf[4][4];
    LOADW(buf[0], wf, 0, warp, lane);
    LOADW(buf[1], wf, 1, warp, lane);
    LOADW(buf[2], wf, 2, warp, lane);
    LOADW(buf[3], wf, 3, warp, lane);

    const float* cbase = g_comb + (size_t)b * FPITCH * MAXO;
    for (int i = tid; i < FPITCH * MAXO; i += 256) {
        float x = cbase[i];
        int feat = i >> 4, obj = i & 15;
        __nv_bfloat16 h, l;
        bsplit(x, h, l);
        A1h[obj * 296 + feat] = h;
        A1l[obj * 296 + feat] = l;
    }
    u_s[tid] = g_u[b * DD + tid];
    q_s[tid] = g_q[b * DD + tid];
    r_s[tid] = g_r[tid];
    bp_s[tid] = bpv[tid];
    gm_s[tid] = gv[tid];
    bt_s[tid] = btv[tid];
    b1_s[tid] = b1v[tid];
    if (tid < MAXO) vld[tid] = g_valid[b * MAXO + tid];
    if (tid == 0) { s_bd[0] = g_bdot[b]; s_bd[1] = osp[0]; }
    __syncthreads();

    // ============ GEMM1: hidden = gelu(A1 @ W1 + b1), 18 tiles ============
    float c1[4][4];
#pragma unroll
    for (int nt = 0; nt < 4; nt++)
#pragma unroll
        for (int j = 0; j < 4; j++) c1[nt][j] = 0.f;

#pragma unroll
    for (int t = 0; t < 18; t++) {
        uint4 q0 = buf[t & 3][0], q1 = buf[t & 3][1];
        uint4 q2 = buf[t & 3][2], q3 = buf[t & 3][3];
        if (t + 4 < 18) LOADW(buf[t & 3], wf, t + 4, warp, lane);

        unsigned ah[4], al[4];
        int k0 = 16 * t + 2 * tl;
        ah[0] = *(const unsigned*)(A1h + g * 296 + k0);
        ah[1] = *(const unsigned*)(A1h + (g + 8) * 296 + k0);
        ah[2] = *(const unsigned*)(A1h + g * 296 + k0 + 8);
        ah[3] = *(const unsigned*)(A1h + (g + 8) * 296 + k0 + 8);
        al[0] = *(const unsigned*)(A1l + g * 296 + k0);
        al[1] = *(const unsigned*)(A1l + (g + 8) * 296 + k0);
        al[2] = *(const unsigned*)(A1l + g * 296 + k0 + 8);
        al[3] = *(const unsigned*)(A1l + (g + 8) * 296 + k0 + 8);

        mma16816(c1[0], ah, q0.x, q0.y);
        mma16816(c1[0], al, q0.x, q0.y);
        mma16816(c1[0], ah, q2.x, q2.y);
        mma16816(c1[1], ah, q0.z, q0.w);
        mma16816(c1[1], al, q0.z, q0.w);
        mma16816(c1[1], ah, q2.z, q2.w);
        mma16816(c1[2], ah, q1.x, q1.y);
        mma16816(c1[2], al, q1.x, q1.y);
        mma16816(c1[2], ah, q3.x, q3.y);
        mma16816(c1[3], ah, q1.z, q1.w);
        mma16816(c1[3], al, q1.z, q1.w);
        mma16816(c1[3], ah, q3.z, q3.w);
    }

    LOADW(buf[0], ef, 0, warp, lane);
    LOADW(buf[1], ef, 1, warp, lane);
    LOADW(buf[2], ef, 2, warp, lane);
    LOADW(buf[3], ef, 3, warp, lane);

    float bdot = s_bd[0], os = s_bd[1];
    float dpA = 0.f, dpB = 0.f;
#pragma unroll
    for (int nt = 0; nt < 4; nt++) {
        int col = (warp * 4 + nt) * 8 + 2 * tl;
        float h0 = gelu(c1[nt][0] + b1_s[col]);
        float h1 = gelu(c1[nt][1] + b1_s[col + 1]);
        float h2 = gelu(c1[nt][2] + b1_s[col]);
        float h3 = gelu(c1[nt][3] + b1_s[col + 1]);
        dpA += h0 * u_s[col] + h1 * u_s[col + 1];
        dpB += h2 * u_s[col] + h3 * u_s[col + 1];
        __nv_bfloat16 e0, f0, e1, f1;
        bsplit(h0, e0, f0); bsplit(h1, e1, f1);
        *(unsigned*)(A2h + g * 264 + col) = bpack2(e0, e1);
        *(unsigned*)(A2l + g * 264 + col) = bpack2(f0, f1);
        bsplit(h2, e0, f0); bsplit(h3, e1, f1);
        *(unsigned*)(A2h + (g + 8) * 264 + col) = bpack2(e0, e1);
        *(unsigned*)(A2l + (g + 8) * 264 + col) = bpack2(f0, f1);
    }
    dpA += __shfl_xor_sync(0xffffffffu, dpA, 1);
    dpA += __shfl_xor_sync(0xffffffffu, dpA, 2);
    dpB += __shfl_xor_sync(0xffffffffu, dpB, 1);
    dpB += __shfl_xor_sync(0xffffffffu, dpB, 2);
    if (tl == 0) {
        redA[g * 8 + warp] = dpA;
        redA[(g + 8) * 8 + warp] = dpB;
    }
    __syncthreads();
    if (tid < MAXO) {
        float s = 0.f;
#pragma unroll
        for (int w = 0; w < 8; w++) s += redA[tid * 8 + w];
        dots[tid] = s + bdot;
    }

    // ============ GEMM2: hE = hidden @ E, 16 tiles ============
    float c2[4][4];
#pragma unroll
    for (int nt = 0; nt < 4; nt++)
#pragma unroll
        for (int j = 0; j < 4; j++) c2[nt][j] = 0.f;

#pragma unroll
    for (int t = 0; t < 16; t++) {
        uint4 q0 = buf[t & 3][0], q1 = buf[t & 3][1];
        uint4 q2 = buf[t & 3][2], q3 = buf[t & 3][3];
        if (t + 4 < 16) LOADW(buf[t & 3], ef, t + 4, warp, lane);

        unsigned ah[4], al[4];
        int k0 = 16 * t + 2 * tl;
        ah[0] = *(const unsigned*)(A2h + g * 264 + k0);
        ah[1] = *(const unsigned*)(A2h + (g + 8) * 264 + k0);
        ah[2] = *(const unsigned*)(A2h + g * 264 + k0 + 8);
        ah[3] = *(const unsigned*)(A2h + (g + 8) * 264 + k0 + 8);
        al[0] = *(const unsigned*)(A2l + g * 264 + k0);
        al[1] = *(const unsigned*)(A2l + (g + 8) * 264 + k0);
        al[2] = *(const unsigned*)(A2l + g * 264 + k0 + 8);
        al[3] = *(const unsigned*)(A2l + (g + 8) * 264 + k0 + 8);

        mma16816(c2[0], ah, q0.x, q0.y);
        mma16816(c2[0], al, q0.x, q0.y);
        mma16816(c2[0], ah, q2.x, q2.y);
        mma16816(c2[1], ah, q0.z, q0.w);
        mma16816(c2[1], al, q0.z, q0.w);
        mma16816(c2[1], ah, q2.z, q2.w);
        mma16816(c2[2], ah, q1.x, q1.y);
        mma16816(c2[2], al, q1.x, q1.y);
        mma16816(c2[2], ah, q3.x, q3.y);
        mma16816(c2[3], ah, q1.z, q1.w);
        mma16816(c2[3], al, q1.z, q1.w);
        mma16816(c2[3], ah, q3.z, q3.w);
    }
    __syncthreads();

    float prer[4][4];
    float dA = dots[g], dB = dots[g + 8];
    int vA = vld[g], vB = vld[g + 8];
#pragma unroll
    for (int nt = 0; nt < 4; nt++) {
        int col = (warp * 4 + nt) * 8 + 2 * tl;
        float r0v = r_s[col], r1v = r_s[col + 1];
        float q0 = q_s[col], q1 = q_s[col + 1];
        float bp0 = bp_s[col], bp1 = bp_s[col + 1];
        float p0 = os * (c2[nt][0] + r0v - dA * q0) + bp0;
        float p1 = os * (c2[nt][1] + r1v - dA * q1) + bp1;
        float p2 = os * (c2[nt][2] + r0v - dB * q0) + bp0;
        float p3 = os * (c2[nt][3] + r1v - dB * q1) + bp1;
        prer[nt][0] = vA ? p0 : bp0;
        prer[nt][1] = vA ? p1 : bp1;
        prer[nt][2] = vB ? p2 : bp0;
        prer[nt][3] = vB ? p3 : bp1;
    }

    float psA = 0.f, pqA = 0.f, psB = 0.f, pqB = 0.f;
#pragma unroll
    for (int nt = 0; nt < 4; nt++) {
        psA += prer[nt][0] + prer[nt][1];
        pqA += prer[nt][0] * prer[nt][0] + prer[nt][1] * prer[nt][1];
        psB += prer[nt][2] + prer[nt][3];
        pqB += prer[nt][2] * prer[nt][2] + prer[nt][3] * prer[nt][3];
    }
    psA += __shfl_xor_sync(0xffffffffu, psA, 1);
    psA += __shfl_xor_sync(0xffffffffu, psA, 2);
    pqA += __shfl_xor_sync(0xffffffffu, pqA, 1);
    pqA += __shfl_xor_sync(0xffffffffu, pqA, 2);
    psB += __shfl_xor_sync(0xffffffffu, psB, 1);
    psB += __shfl_xor_sync(0xffffffffu, psB, 2);
    pqB += __shfl_xor_sync(0xffffffffu, pqB, 1);
    pqB += __shfl_xor_sync(0xffffffffu, pqB, 2);
    if (tl == 0) {
        redA[g * 8 + warp] = psA;
        redA[(g + 8) * 8 + warp] = psB;
        redB[g * 8 + warp] = pqA;
        redB[(g + 8) * 8 + warp] = pqB;
    }
    __syncthreads();
    if (tid < MAXO) {
        float s = 0.f, sq = 0.f;
#pragma unroll
        for (int w = 0; w < 8; w++) { s += redA[tid * 8 + w]; sq += redB[tid * 8 + w]; }
        float m = s * (1.0f / DD);
        mur[tid] = m;
        float va = sq * (1.0f / DD) - m * m;
        rstd[tid] = rsqrtf(va + 1e-5f);
    }
    __syncthreads();

    float mA = mur[g], rsA = rstd[g], mB = mur[g + 8], rsB = rstd[g + 8];
#pragma unroll
    for (int nt = 0; nt < 4; nt++) {
        int col = (warp * 4 + nt) * 8 + 2 * tl;
        float g0 = gm_s[col], g1 = gm_s[col + 1];
        float t0 = bt_s[col], t1 = bt_s[col + 1];
        float2 o0, o1;
        o0.x = (prer[nt][0] - mA) * rsA * g0 + t0;
        o0.y = (prer[nt][1] - mA) * rsA * g1 + t1;
        o1.x = (prer[nt][2] - mB) * rsB * g0 + t0;
        o1.y = (prer[nt][3] - mB) * rsB * g1 + t1;
        *(float2*)&out[((size_t)(b * MAXO + g)) * DD + col] = o0;
        *(float2*)&out[((size_t)(b * MAXO + g + 8)) * DD + col] = o1;
    }
}

#define MLP_SMEM 44032

// =========================================================================
extern "C" void kernel_launch(void* const* d_in, const int* in_sizes, int n_in,
                              void* d_out, int out_size) {
    const float* grid_emb = (const float*)d_in[0];
    const int*   grid     = (const int*)d_in[1];
    const float* sr       = (const float*)d_in[2];
    const float* W1       = (const float*)d_in[3];
    const float* b1       = (const float*)d_in[4];
    const float* W2       = (const float*)d_in[5];
    const float* b2       = (const float*)d_in[6];
    const float* Wp       = (const float*)d_in[7];
    const float* bp       = (const float*)d_in[8];
    const float* gamma    = (const float*)d_in[9];
    const float* beta     = (const float*)d_in[10];
    const float* os       = (const float*)d_in[11];

    cudaFuncSetAttribute(mlp_kernel, cudaFuncAttributeMaxDynamicSharedMemorySize, MLP_SMEM);

    pre_kernel<<<PRE_GRID, 1024>>>(grid_emb, grid, sr, W1, W2, Wp, b2);
    mlp_kernel<<<BB, 256, MLP_SMEM>>>(b1, gamma, beta, bp, os, (float*)d_out);
}

// round 17
// speedup vs baseline: 1.7385x; 1.0012x over previous
#include <cuda_runtime.h>
#include <cuda_bf16.h>
#include <math.h>

#define HH 30
#define WWG 30
#define HW 900
#define DD 256
#define MAXO 16
#define BB 128
#define FPITCH 288   // 261 feature rows padded to 288 (18 K-tiles of 16)
#define CHUNK 1024
#define PF 16

#define BAR(id, cnt) asm volatile("bar.sync %0, %1;" :: "r"(id), "r"(cnt) : "memory")

// ---------------- device scratch ----------------
__device__ __align__(16) float g_comb[BB * FPITCH * MAXO];  // [b][feat][k]
__device__ __align__(16) float g_u[BB * DD];
__device__ __align__(16) float g_q[BB * DD];
__device__ float g_bdot[BB];
__device__ __align__(16) float g_r[DD];                     // b2 @ Wp
__device__ int   g_valid[BB * MAXO];
// interleaved fragment-shuffled bf16 weights:
// [(t*8+w)*32+lane] -> 32 bf16 = [qh0(8) | qh1(8) | ql0(8) | ql1(8)]
__device__ __align__(16) __nv_bfloat16 g_W1f[18 * 8 * 32 * 32];
__device__ __align__(16) __nv_bfloat16 g_Ef[16 * 8 * 32 * 32];

__device__ __forceinline__ void bsplit(float x, __nv_bfloat16& h, __nv_bfloat16& l) {
    h = __float2bfloat16(x);
    l = __float2bfloat16(x - __bfloat162float(h));
}
__device__ __forceinline__ unsigned bpack2(__nv_bfloat16 a, __nv_bfloat16 b) {
    return ((unsigned)__bfloat16_as_ushort(b) << 16) | __bfloat16_as_ushort(a);
}
__device__ __forceinline__ void mma16816(float c[4], const unsigned a[4],
                                         unsigned b0, unsigned b1) {
    asm volatile(
        "mma.sync.aligned.m16n8k16.row.col.f32.bf16.bf16.f32 "
        "{%0,%1,%2,%3},{%4,%5,%6,%7},{%8,%9},{%0,%1,%2,%3};"
        : "+f"(c[0]), "+f"(c[1]), "+f"(c[2]), "+f"(c[3])
        : "r"(a[0]), "r"(a[1]), "r"(a[2]), "r"(a[3]), "r"(b0), "r"(b1));
}
__device__ __forceinline__ float gelu(float x) {
    return 0.5f * x * (1.0f + erff(x * 0.70710678118654752f));
}
// weight element (k,n,islo) -> interleaved fragment index (bf16 units)
__device__ __forceinline__ size_t fragidx2(int k, int n, int islo) {
    int t = k >> 4, kk = k & 15;
    int w = n >> 5, nt = (n >> 3) & 3, gq = n & 7;
    int bsel = kk >> 3, tl2 = (kk & 7) >> 1, half = kk & 1;
    int lane = gq * 4 + tl2;
    int sub = islo * 16 + (nt >> 1) * 8 + (nt & 1) * 4 + bsel * 2 + half;
    return (((size_t)(t * 8 + w) * 32 + lane) * 32) + sub;
}

// =========================================================================
// Single-wave warp-specialized pre-kernel. 128 blocks x 1024 threads.
// warps 0-7: CCL (bar 1); warps 8-15: prep (bar 2);
// warps 16-31: W1-pad + 2 E rows (+ r) (bar 3), then JOIN pooling.
// Pooling runs on groups A+C = 768 threads (bar 4): 3 entry-groups x 256 ch.
// =========================================================================
__global__ __launch_bounds__(1024) void pre_kernel(const float* __restrict__ grid_emb,
                                                   const int* __restrict__ grid,
                                                   const float* __restrict__ sr,
                                                   const float* __restrict__ W1,
                                                   const float* __restrict__ W2,
                                                   const float* __restrict__ Wp,
                                                   const float* __restrict__ b2) {
    int b = blockIdx.x, tid = threadIdx.x;

    __shared__ __align__(16) char spool[35392];
    __shared__ unsigned rootbits[32];
    __shared__ int wpre[32];
    __shared__ int s_flag[2];
    __shared__ int nvalid;
    __shared__ int robj[MAXO], rmin[MAXO], rmax[MAXO], cmin[MAXO], cmax[MAXO];
    __shared__ int offs[MAXO + 1];

    int* g       = (int*)spool;                    // 3600
    int* lab     = g + HW;                         // 3600
    int* slot_of = lab + HW;                       // 3600 -> 10800
    float* fpool = (float*)(spool + 10816);        // 16384 -> 27200
    int* ipool   = (int*)(spool + 27200);          // 4096  -> 31296
    float* sn    = (float*)(spool + 31296);        // 1024
    float* sred  = (float*)(spool + 32320);        // 1024
    float* w2s2  = (float*)(spool + 33344);        // 2048

    if (tid < 256 || tid >= 512) {
        // unified pooling identity for groups A and C
        int uidx = (tid < 256) ? tid : (tid - 256);       // 0..767
        int ch = uidx & 255;
        int grp = uidx >> 8;                              // A:0, C:1,2

        if (tid < 256) {
            // ================= GROUP A: CCL (proven) =================
            for (int c = tid; c < HW; c += 256) {
                int v = grid[b * HW + c];
                g[c] = v;
                lab[c] = (v > 0) ? c : HW;
                slot_of[c] = -1;
            }
            if (tid < 32) rootbits[tid] = 0;
            if (tid == 0) { s_flag[0] = 0; s_flag[1] = 0; }
            BAR(1, 256);

            for (int it = 0; it < 512; it++) {
                int f = it & 1;
                if (tid == 0) s_flag[1 - f] = 0;
                int changed = 0;
                for (int c = tid; c < HW; c += 256) {
                    int gc = g[c];
                    if (gc > 0) {
                        int m = lab[c];
                        int col = c % WWG;
                        if (c >= WWG && g[c - WWG] == gc) { int t = lab[c - WWG]; if (t < m) m = t; }
                        if (c < HW - WWG && g[c + WWG] == gc) { int t = lab[c + WWG]; if (t < m) m = t; }
                        if (col > 0 && g[c - 1] == gc) { int t = lab[c - 1]; if (t < m) m = t; }
                        if (col < WWG - 1 && g[c + 1] == gc) { int t = lab[c + 1]; if (t < m) m = t; }
#pragma unroll
                        for (int hop = 0; hop < 8; hop++) {
                            int p = lab[m];
                            if (p >= m) break;
                            m = p;
                        }
                        if (m < lab[c]) { lab[c] = m; changed = 1; }
                    }
                }
                if (changed) s_flag[f] = 1;
                BAR(1, 256);
                int chg = s_flag[f];
                BAR(1, 256);
                if (!chg) break;
            }

            for (int c = tid; c < HW; c += 256)
                if (g[c] > 0 && lab[c] == c) atomicOr(&rootbits[c >> 5], 1u << (c & 31));
            BAR(1, 256);
            if (tid == 0) {
                int s = 0;
                for (int w = 0; w < 29; w++) { wpre[w] = s; s += __popc(rootbits[w]); }
                nvalid = s < MAXO ? s : MAXO;
            }
            BAR(1, 256);
            for (int c = tid; c < HW; c += 256) {
                if (g[c] > 0 && lab[c] == c) {
                    int w = c >> 5;
                    int rank = wpre[w] + __popc(rootbits[w] & ((1u << (c & 31)) - 1u));
                    if (rank < MAXO) { robj[rank] = c; slot_of[c] = rank; }
                }
            }
            if (tid < MAXO) { rmin[tid] = HH; rmax[tid] = -1; cmin[tid] = WWG; cmax[tid] = -1; }
            BAR(1, 256);
            for (int c = tid; c < HW; c += 256) {
                if (g[c] > 0) {
                    int s = slot_of[lab[c]];
                    if (s >= 0) {
                        int r = c / WWG, col = c % WWG;
                        atomicMin(&rmin[s], r); atomicMax(&rmax[s], r);
                        atomicMin(&cmin[s], col); atomicMax(&cmax[s], col);
                    }
                }
            }
            BAR(1, 256);
            if (tid == 0) {
                int nv = nvalid, off = 0;
                for (int k = 0; k < nv; k++) {
                    offs[k] = off;
                    off += (rmax[k] + 1 - rmin[k]) * (cmax[k] + 1 - cmin[k]);
                }
                offs[nv] = off;
            }
            for (int i = tid; i < MAXO * DD; i += 256) fpool[i] = 0.f;
        } else {
            // ============ GROUP C: W1-pad + 2 E rows (+ r) ============
            int t3 = tid - 512;
            if (t3 < 144) {
                int i = b * 144 + t3;
                const float4* w14 = (const float4*)W1;
                float4 v = make_float4(0.f, 0.f, 0.f, 0.f);
                if (i < 16704) v = w14[i];
                int k = i >> 6;
                int n0 = (i & 63) * 4;
                float vals[4] = {v.x, v.y, v.z, v.w};
#pragma unroll
                for (int c = 0; c < 4; c++) {
                    __nv_bfloat16 h, l;
                    bsplit(vals[c], h, l);
                    g_W1f[fragidx2(k, n0 + c, 0)] = h;
                    g_W1f[fragidx2(k, n0 + c, 1)] = l;
                }
            }
            int d0 = 2 * b;
            for (int i = t3; i < 2 * DD; i += 512) w2s2[i] = W2[d0 * DD + i];
            BAR(3, 512);
            int e = t3 & 255, sub = t3 >> 8;
            const float* w2row = w2s2 + sub * DD;
            float acc = 0.f;
#pragma unroll 8
            for (int k = 0; k < DD; k++) acc += w2row[k] * Wp[k * DD + e];
            __nv_bfloat16 h, l;
            bsplit(acc, h, l);
            g_Ef[fragidx2(d0 + sub, e, 0)] = h;
            g_Ef[fragidx2(d0 + sub, e, 1)] = l;
            if (b == BB - 1 && t3 < DD) {
                float a = 0.f;
#pragma unroll 8
                for (int k = 0; k < DD; k++) a += b2[k] * Wp[k * DD + t3];
                g_r[t3] = a;
            }
        }

        // ============ JOINT POOLING: 768 threads (A + C) ============
        BAR(4, 768);   // offs/bboxes/fpool-zero ready; C's side work done
        int nv = nvalid;
        int total = offs[nv];
        const float* gbase = grid_emb + (size_t)b * HW * DD + ch;
        for (int base = 0; base < total; base += CHUNK) {
            int n = min(CHUNK, total - base);
            for (int e = uidx; e < n; e += 768) {
                int ge = base + e;
                int k = 0;
                while (k + 1 < nv && ge >= offs[k + 1]) k++;
                int local = ge - offs[k];
                int bw = cmax[k] + 1 - cmin[k];
                int li = local / bw, lj = local - li * bw;
                int cell = (rmin[k] + li) * WWG + cmin[k] + lj;
                ipool[e] = (k << 16) | cell;
            }
            BAR(4, 768);
            int n3 = (n + 2) / 3;
            int s0 = grp * n3, s1 = min(n, s0 + n3);
            float run = 0.f;
            int prev = -1;
            for (int e0b = s0; e0b < s1; e0b += PF) {
                int m = s1 - e0b; if (m > PF) m = PF;
                float v[PF]; int kk[PF];
#pragma unroll
                for (int j = 0; j < PF; j++) {
                    if (j < m) {
                        int ent = ipool[e0b + j];
                        kk[j] = ent >> 16;
                        v[j] = gbase[(size_t)(ent & 0xffff) * DD];
                    }
                }
#pragma unroll
                for (int j = 0; j < PF; j++) {
                    if (j < m) {
                        if (kk[j] != prev) {
                            if (prev >= 0) atomicAdd(&fpool[prev * DD + ch], run);
                            run = 0.f;
                            prev = kk[j];
                        }
                        run += v[j];
                    }
                }
            }
            if (prev >= 0) atomicAdd(&fpool[prev * DD + ch], run);
            BAR(4, 768);
        }

        // ============ GROUP A finishes: features ============
        if (tid < 256) {
            float* cb = g_comb + (size_t)b * FPITCH * MAXO;
            for (int i = tid; i < FPITCH * MAXO; i += 256) cb[i] = 0.f;
            if (tid < MAXO) g_valid[b * MAXO + tid] = (tid < nv) ? 1 : 0;
            BAR(1, 256);
            for (int k = 0; k < nv; k++) {
                int y = rmin[k], x = cmin[k];
                int h = rmax[k] + 1 - y, w = cmax[k] + 1 - x;
                cb[tid * MAXO + k] = fpool[k * DD + tid] / (float)(h * w);
                if (tid < 5) {
                    float v;
                    int color = g[robj[k]];
                    if (tid == 0)      v = (float)color * (1.0f / 9.0f);
                    else if (tid == 1) v = (float)x * (1.0f / WWG);
                    else if (tid == 2) v = (float)y * (1.0f / HH);
                    else if (tid == 3) v = (float)w * (1.0f / WWG);
                    else               v = (float)h * (1.0f / HH);
                    cb[(DD + tid) * MAXO + k] = v;
                }
            }
        }
    } else {
        // ================= GROUP B: prep (proven) =================
        int t2 = tid - 256;
        float s = 0.f;
        const float* base = sr + (size_t)b * 8 * DD + t2;
#pragma unroll
        for (int j = 0; j < 8; j++) s += base[j * DD];
        s *= 0.125f;
        sred[t2] = s * s; BAR(2, 256);
        for (int off = 128; off; off >>= 1) {
            if (t2 < off) sred[t2] += sred[t2 + off];
            BAR(2, 256);
        }
        float nrm = sqrtf(sred[0]);
        BAR(2, 256);
        float snv = s / fmaxf(nrm, 1e-8f);
        sn[t2] = snv;
        sred[t2] = snv * b2[t2]; BAR(2, 256);
        for (int off = 128; off; off >>= 1) {
            if (t2 < off) sred[t2] += sred[t2 + off];
            BAR(2, 256);
        }
        if (t2 == 0) g_bdot[b] = sred[0];

        float acc = 0.f;
#pragma unroll 8
        for (int d = 0; d < DD; d++) acc += sn[d] * Wp[d * DD + t2];
        g_q[b * DD + t2] = acc;

        int wid = t2 >> 5, lane = t2 & 31;
        for (int d = wid; d < DD; d += 8) {
            float a = 0.f;
            const float* wr = W2 + d * DD;
#pragma unroll 4
            for (int e2 = lane; e2 < DD; e2 += 32) a += wr[e2] * sn[e2];
#pragma unroll
            for (int off = 16; off; off >>= 1) a += __shfl_down_sync(0xffffffffu, a, off);
            if (lane == 0) g_u[b * DD + d] = a;
        }
    }
}
#define PRE_GRID BB   // 128 blocks, one wave

// per-thread 64B weight block load (4 x LDG.128 at immediate offsets)
#define LOADW(dst, arr, t, warp, lane)                                      \
    {                                                                       \
        const uint4* _p = (arr) + (((size_t)(t) * 8 + (warp)) * 32 + (lane)) * 4; \
        (dst)[0] = _p[0]; (dst)[1] = _p[1]; (dst)[2] = _p[2]; (dst)[3] = _p[3];   \
    }

// =========================================================================
// Tensor-core MLP (R15/R16-proven): interleaved fragment-streamed weights,
// depth-4 software pipeline, no barriers in GEMM loops.
// =========================================================================
__global__ __launch_bounds__(256) void mlp_kernel(const float* __restrict__ b1v,
                                                  const float* __restrict__ gv,
                                                  const float* __restrict__ btv,
                                                  const float* __restrict__ bpv,
                                                  const float* __restrict__ osp,
                                                  float* __restrict__ out) {
    int b = blockIdx.x, tid = threadIdx.x;
    int warp = tid >> 5, lane = tid & 31;
    int g = lane >> 2, tl = lane & 3;

    extern __shared__ char smraw[];
    __nv_bfloat16* A1h = (__nv_bfloat16*)(smraw);            // 16 x 296
    __nv_bfloat16* A1l = (__nv_bfloat16*)(smraw + 9472);
    __nv_bfloat16* A2h = (__nv_bfloat16*)(smraw + 18944);    // 16 x 264
    __nv_bfloat16* A2l = (__nv_bfloat16*)(smraw + 27392);
    float* u_s  = (float*)(smraw + 35840);
    float* q_s  = (float*)(smraw + 36864);
    float* r_s  = (float*)(smraw + 37888);
    float* bp_s = (float*)(smraw + 38912);
    float* gm_s = (float*)(smraw + 39936);
    float* bt_s = (float*)(smraw + 40960);
    float* b1_s = (float*)(smraw + 41984);
    float* redA = (float*)(smraw + 43008);   // [16][8]
    float* redB = (float*)(smraw + 43520);   // [16][8]
    __shared__ float dots[MAXO], mur[MAXO], rstd[MAXO], s_bd[2];
    __shared__ int vld[MAXO];

    const uint4* wf = (const uint4*)g_W1f;
    const uint4* ef = (const uint4*)g_Ef;

    uint4 buf[4][4];
    LOADW(buf[0], wf, 0, warp, lane);
    LOADW(buf[1], wf, 1, warp, lane);
    LOADW(buf[2], wf, 2, warp, lane);
    LOADW(buf[3], wf, 3, warp, lane);

    const float* cbase = g_comb + (size_t)b * FPITCH * MAXO;
    for (int i = tid; i < FPITCH * MAXO; i += 256) {
        float x = cbase[i];
        int feat = i >> 4, obj = i & 15;
        __nv_bfloat16 h, l;
        bsplit(x, h, l);
        A1h[obj * 296 + feat] = h;
        A1l[obj * 296 + feat] = l;
    }
    u_s[tid] = g_u[b * DD + tid];
    q_s[tid] = g_q[b * DD + tid];
    r_s[tid] = g_r[tid];
    bp_s[tid] = bpv[tid];
    gm_s[tid] = gv[tid];
    bt_s[tid] = btv[tid];
    b1_s[tid] = b1v[tid];
    if (tid < MAXO) vld[tid] = g_valid[b * MAXO + tid];
    if (tid == 0) { s_bd[0] = g_bdot[b]; s_bd[1] = osp[0]; }
    __syncthreads();

    // ============ GEMM1: hidden = gelu(A1 @ W1 + b1), 18 tiles ============
    float c1[4][4];
#pragma unroll
    for (int nt = 0; nt < 4; nt++)
#pragma unroll
        for (int j = 0; j < 4; j++) c1[nt][j] = 0.f;

#pragma unroll
    for (int t = 0; t < 18; t++) {
        uint4 q0 = buf[t & 3][0], q1 = buf[t & 3][1];
        uint4 q2 = buf[t & 3][2], q3 = buf[t & 3][3];
        if (t + 4 < 18) LOADW(buf[t & 3], wf, t + 4, warp, lane);

        unsigned ah[4], al[4];
        int k0 = 16 * t + 2 * tl;
        ah[0] = *(const unsigned*)(A1h + g * 296 + k0);
        ah[1] = *(const unsigned*)(A1h + (g + 8) * 296 + k0);
        ah[2] = *(const unsigned*)(A1h + g * 296 + k0 + 8);
        ah[3] = *(const unsigned*)(A1h + (g + 8) * 296 + k0 + 8);
        al[0] = *(const unsigned*)(A1l + g * 296 + k0);
        al[1] = *(const unsigned*)(A1l + (g + 8) * 296 + k0);
        al[2] = *(const unsigned*)(A1l + g * 296 + k0 + 8);
        al[3] = *(const unsigned*)(A1l + (g + 8) * 296 + k0 + 8);

        mma16816(c1[0], ah, q0.x, q0.y);
        mma16816(c1[0], al, q0.x, q0.y);
        mma16816(c1[0], ah, q2.x, q2.y);
        mma16816(c1[1], ah, q0.z, q0.w);
        mma16816(c1[1], al, q0.z, q0.w);
        mma16816(c1[1], ah, q2.z, q2.w);
        mma16816(c1[2], ah, q1.x, q1.y);
        mma16816(c1[2], al, q1.x, q1.y);
        mma16816(c1[2], ah, q3.x, q3.y);
        mma16816(c1[3], ah, q1.z, q1.w);
        mma16816(c1[3], al, q1.z, q1.w);
        mma16816(c1[3], ah, q3.z, q3.w);
    }

    LOADW(buf[0], ef, 0, warp, lane);
    LOADW(buf[1], ef, 1, warp, lane);
    LOADW(buf[2], ef, 2, warp, lane);
    LOADW(buf[3], ef, 3, warp, lane);

    float bdot = s_bd[0], os = s_bd[1];
    float dpA = 0.f, dpB = 0.f;
#pragma unroll
    for (int nt = 0; nt < 4; nt++) {
        int col = (warp * 4 + nt) * 8 + 2 * tl;
        float h0 = gelu(c1[nt][0] + b1_s[col]);
        float h1 = gelu(c1[nt][1] + b1_s[col + 1]);
        float h2 = gelu(c1[nt][2] + b1_s[col]);
        float h3 = gelu(c1[nt][3] + b1_s[col + 1]);
        dpA += h0 * u_s[col] + h1 * u_s[col + 1];
        dpB += h2 * u_s[col] + h3 * u_s[col + 1];
        __nv_bfloat16 e0, f0, e1, f1;
        bsplit(h0, e0, f0); bsplit(h1, e1, f1);
        *(unsigned*)(A2h + g * 264 + col) = bpack2(e0, e1);
        *(unsigned*)(A2l + g * 264 + col) = bpack2(f0, f1);
        bsplit(h2, e0, f0); bsplit(h3, e1, f1);
        *(unsigned*)(A2h + (g + 8) * 264 + col) = bpack2(e0, e1);
        *(unsigned*)(A2l + (g + 8) * 264 + col) = bpack2(f0, f1);
    }
    dpA += __shfl_xor_sync(0xffffffffu, dpA, 1);
    dpA += __shfl_xor_sync(0xffffffffu, dpA, 2);
    dpB += __shfl_xor_sync(0xffffffffu, dpB, 1);
    dpB += __shfl_xor_sync(0xffffffffu, dpB, 2);
    if (tl == 0) {
        redA[g * 8 + warp] = dpA;
        redA[(g + 8) * 8 + warp] = dpB;
    }
    __syncthreads();
    if (tid < MAXO) {
        float s = 0.f;
#pragma unroll
        for (int w = 0; w < 8; w++) s += redA[tid * 8 + w];
        dots[tid] = s + bdot;
    }

    // ============ GEMM2: hE = hidden @ E, 16 tiles ============
    float c2[4][4];
#pragma unroll
    for (int nt = 0; nt < 4; nt++)
#pragma unroll
        for (int j = 0; j < 4; j++) c2[nt][j] = 0.f;

#pragma unroll
    for (int t = 0; t < 16; t++) {
        uint4 q0 = buf[t & 3][0], q1 = buf[t & 3][1];
        uint4 q2 = buf[t & 3][2], q3 = buf[t & 3][3];
        if (t + 4 < 16) LOADW(buf[t & 3], ef, t + 4, warp, lane);

        unsigned ah[4], al[4];
        int k0 = 16 * t + 2 * tl;
        ah[0] = *(const unsigned*)(A2h + g * 264 + k0);
        ah[1] = *(const unsigned*)(A2h + (g + 8) * 264 + k0);
        ah[2] = *(const unsigned*)(A2h + g * 264 + k0 + 8);
        ah[3] = *(const unsigned*)(A2h + (g + 8) * 264 + k0 + 8);
        al[0] = *(const unsigned*)(A2l + g * 264 + k0);
        al[1] = *(const unsigned*)(A2l + (g + 8) * 264 + k0);
        al[2] = *(const unsigned*)(A2l + g * 264 + k0 + 8);
        al[3] = *(const unsigned*)(A2l + (g + 8) * 264 + k0 + 8);

        mma16816(c2[0], ah, q0.x, q0.y);
        mma16816(c2[0], al, q0.x, q0.y);
        mma16816(c2[0], ah, q2.x, q2.y);
        mma16816(c2[1], ah, q0.z, q0.w);
        mma16816(c2[1], al, q0.z, q0.w);
        mma16816(c2[1], ah, q2.z, q2.w);
        mma16816(c2[2], ah, q1.x, q1.y);
        mma16816(c2[2], al, q1.x, q1.y);
        mma16816(c2[2], ah, q3.x, q3.y);
        mma16816(c2[3], ah, q1.z, q1.w);
        mma16816(c2[3], al, q1.z, q1.w);
        mma16816(c2[3], ah, q3.z, q3.w);
    }
    __syncthreads();

    float prer[4][4];
    float dA = dots[g], dB = dots[g + 8];
    int vA = vld[g], vB = vld[g + 8];
#pragma unroll
    for (int nt = 0; nt < 4; nt++) {
        int col = (warp * 4 + nt) * 8 + 2 * tl;
        float r0v = r_s[col], r1v = r_s[col + 1];
        float q0 = q_s[col], q1 = q_s[col + 1];
        float bp0 = bp_s[col], bp1 = bp_s[col + 1];
        float p0 = os * (c2[nt][0] + r0v - dA * q0) + bp0;
        float p1 = os * (c2[nt][1] + r1v - dA * q1) + bp1;
        float p2 = os * (c2[nt][2] + r0v - dB * q0) + bp0;
        float p3 = os * (c2[nt][3] + r1v - dB * q1) + bp1;
        prer[nt][0] = vA ? p0 : bp0;
        prer[nt][1] = vA ? p1 : bp1;
        prer[nt][2] = vB ? p2 : bp0;
        prer[nt][3] = vB ? p3 : bp1;
    }

    float psA = 0.f, pqA = 0.f, psB = 0.f, pqB = 0.f;
#pragma unroll
    for (int nt = 0; nt < 4; nt++) {
        psA += prer[nt][0] + prer[nt][1];
        pqA += prer[nt][0] * prer[nt][0] + prer[nt][1] * prer[nt][1];
        psB += prer[nt][2] + prer[nt][3];
        pqB += prer[nt][2] * prer[nt][2] + prer[nt][3] * prer[nt][3];
    }
    psA += __shfl_xor_sync(0xffffffffu, psA, 1);
    psA += __shfl_xor_sync(0xffffffffu, psA, 2);
    pqA += __shfl_xor_sync(0xffffffffu, pqA, 1);
    pqA += __shfl_xor_sync(0xffffffffu, pqA, 2);
    psB += __shfl_xor_sync(0xffffffffu, psB, 1);
    psB += __shfl_xor_sync(0xffffffffu, psB, 2);
    pqB += __shfl_xor_sync(0xffffffffu, pqB, 1);
    pqB += __shfl_xor_sync(0xffffffffu, pqB, 2);
    if (tl == 0) {
        redA[g * 8 + warp] = psA;
        redA[(g + 8) * 8 + warp] = psB;
        redB[g * 8 + warp] = pqA;
        redB[(g + 8) * 8 + warp] = pqB;
    }
    __syncthreads();
    if (tid < MAXO) {
        float s = 0.f, sq = 0.f;
#pragma unroll
        for (int w = 0; w < 8; w++) { s += redA[tid * 8 + w]; sq += redB[tid * 8 + w]; }
        float m = s * (1.0f / DD);
        mur[tid] = m;
        float va = sq * (1.0f / DD) - m * m;
        rstd[tid] = rsqrtf(va + 1e-5f);
    }
    __syncthreads();

    float mA = mur[g], rsA = rstd[g], mB = mur[g + 8], rsB = rstd[g + 8];
#pragma unroll
    for (int nt = 0; nt < 4; nt++) {
        int col = (warp * 4 + nt) * 8 + 2 * tl;
        float g0 = gm_s[col], g1 = gm_s[col + 1];
        float t0 = bt_s[col], t1 = bt_s[col + 1];
        float2 o0, o1;
        o0.x = (prer[nt][0] - mA) * rsA * g0 + t0;
        o0.y = (prer[nt][1] - mA) * rsA * g1 + t1;
        o1.x = (prer[nt][2] - mB) * rsB * g0 + t0;
        o1.y = (prer[nt][3] - mB) * rsB * g1 + t1;
        *(float2*)&out[((size_t)(b * MAXO + g)) * DD + col] = o0;
        *(float2*)&out[((size_t)(b * MAXO + g + 8)) * DD + col] = o1;
    }
}

#define MLP_SMEM 44032

// =========================================================================
extern "C" void kernel_launch(void* const* d_in, const int* in_sizes, int n_in,
                              void* d_out, int out_size) {
    const float* grid_emb = (const float*)d_in[0];
    const int*   grid     = (const int*)d_in[1];
    const float* sr       = (const float*)d_in[2];
    const float* W1       = (const float*)d_in[3];
    const float* b1       = (const float*)d_in[4];
    const float* W2       = (const float*)d_in[5];
    const float* b2       = (const float*)d_in[6];
    const float* Wp       = (const float*)d_in[7];
    const float* bp       = (const float*)d_in[8];
    const float* gamma    = (const float*)d_in[9];
    const float* beta     = (const float*)d_in[10];
    const float* os       = (const float*)d_in[11];

    cudaFuncSetAttribute(mlp_kernel, cudaFuncAttributeMaxDynamicSharedMemorySize, MLP_SMEM);

    pre_kernel<<<PRE_GRID, 1024>>>(grid_emb, grid, sr, W1, W2, Wp, b2);
    mlp_kernel<<<BB, 256, MLP_SMEM>>>(b1, gamma, beta, bp, os, (float*)d_out);
}